// round 4
// baseline (speedup 1.0000x reference)
#include <cuda_runtime.h>
#include <cuda_bf16.h>
#include <cstdint>

// Problem constants
#define MB   256          // meta batch
#define NN   512          // num_sample
#define DD   128          // feat_dim
#define C1   256          // 2*D
#define C2   128          // base_c
#define MTOT (MB * NN)    // 131072 rows

// ---------------- scratch (static __device__) ----------------
__device__ float  g_X[(size_t)MTOT * C1];     // concat[aggr_feat, aggr_inst]
__device__ float  g_Y1[(size_t)MTOT * C1];    // GEMM1 output (bn1+lrelu in place)
__device__ float  g_invS[2 * (size_t)MTOT];   // 1 / masked row sums, per edge type
__device__ double g_partd[256 * 2 * C1];      // per-block stats partials (fp64)
__device__ float  g_ab[2 * C1 + 2 * C2];      // [a1(256) c1(256) a2(128) c2(128)]

__device__ __forceinline__ float lrelu(float y) { return y >= 0.f ? y : 0.01f * y; }

// ============================================================
// K0: masked row sums ->  invS[ez,b,i] = 1/max(sum_j E[i,j] - E[i,i], 1e-12)
// ============================================================
__global__ __launch_bounds__(256) void k_rowsum(
    const float* __restrict__ E0, const float* __restrict__ E1)
{
    const int b  = blockIdx.y;
    const int ez = blockIdx.z;
    const float* __restrict__ E = (ez ? E1 : E0) + (size_t)b * NN * NN;

    const int warp = threadIdx.x >> 5;
    const int lane = threadIdx.x & 31;
    const int row  = blockIdx.x * 8 + warp;

    const float* __restrict__ Er = E + (size_t)row * NN;
    float s = 0.f;
#pragma unroll
    for (int k = 0; k < NN; k += 32) s += Er[k + lane];
#pragma unroll
    for (int off = 16; off > 0; off >>= 1)
        s += __shfl_down_sync(0xffffffffu, s, off);
    if (lane == 0) {
        float sm = s - Er[row];   // remove diagonal
        g_invS[(size_t)ez * MTOT + (size_t)b * NN + row] =
            1.0f / fmaxf(sm, 1e-12f);
    }
}

// ============================================================
// K1: aggregation GEMM on the PRE-NORMALIZED masked edge:
//   w[i,j] = (j==i ? 0 : E[i,j]) * invS[i];  aggr = w @ P  -> g_X
//   per block: 64 rows x 128 cols, grid (8, MB, 2), 256 threads
// ============================================================
__global__ __launch_bounds__(256) void k1_aggr(
    const float* __restrict__ E0, const float* __restrict__ E1,
    const float* __restrict__ P)
{
    __shared__ float sE[64][33];
    __shared__ float sP[32][128];
    __shared__ float sInv[64];

    const int b   = blockIdx.y;
    const int rt  = blockIdx.x;
    const int ez  = blockIdx.z;
    const float* __restrict__ E  = (ez ? E1 : E0) + (size_t)b * NN * NN;
    const float* __restrict__ Pb = P + (size_t)b * NN * DD;
    const int row0 = rt * 64;

    const int tid = threadIdx.x;
    const int tx  = tid & 15;       // col group (8 cols)
    const int ty  = tid >> 4;       // row group (4 rows)

    if (tid < 64)
        sInv[tid] = g_invS[(size_t)ez * MTOT + (size_t)b * NN + row0 + tid];
    __syncthreads();

    float acc[4][8];
#pragma unroll
    for (int r = 0; r < 4; r++)
#pragma unroll
        for (int c = 0; c < 8; c++) acc[r][c] = 0.f;

    for (int k0 = 0; k0 < NN; k0 += 32) {
        // E tile 64x32: mask diagonal, scale by invS  (scalar, coalesced)
#pragma unroll
        for (int l = 0; l < 8; l++) {
            int idx = l * 256 + tid;      // 0..2047
            int r   = idx >> 5;           // 0..63
            int c   = idx & 31;           // 0..31
            int grow = row0 + r, gcol = k0 + c;
            float e = E[(size_t)grow * NN + gcol];
            sE[r][c] = (grow == gcol) ? 0.f : e * sInv[r];
        }
        // P tile 32x128
#pragma unroll
        for (int l = 0; l < 4; l++) {
            int idx = l * 256 + tid;
            int r   = idx >> 5;
            int c4  = (idx & 31) * 4;
            *(float4*)&sP[r][c4] = *(const float4*)(Pb + (size_t)(k0 + r) * DD + c4);
        }
        __syncthreads();

#pragma unroll
        for (int kk = 0; kk < 32; kk++) {
            float a[4], bb[8];
#pragma unroll
            for (int r = 0; r < 4; r++) a[r] = sE[ty * 4 + r][kk];
            *(float4*)&bb[0] = *(const float4*)&sP[kk][tx * 8];
            *(float4*)&bb[4] = *(const float4*)&sP[kk][tx * 8 + 4];
#pragma unroll
            for (int r = 0; r < 4; r++)
#pragma unroll
                for (int c = 0; c < 8; c++) acc[r][c] += a[r] * bb[c];
        }
        __syncthreads();
    }

    const int coff = ez * DD;
#pragma unroll
    for (int r = 0; r < 4; r++) {
        const int grow = row0 + ty * 4 + r;
        float* dst = g_X + ((size_t)b * NN + grow) * C1 + coff + tx * 8;
        float4 o0, o1;
        o0.x = acc[r][0]; o0.y = acc[r][1]; o0.z = acc[r][2]; o0.w = acc[r][3];
        o1.x = acc[r][4]; o1.y = acc[r][5]; o1.z = acc[r][6]; o1.w = acc[r][7];
        *(float4*)dst = o0;
        *(float4*)(dst + 4) = o1;
    }
}

// ============================================================
// GEMM  Y[m,o] = sum_c A[m,c] * W[o,c]
//   A/Y selected INSIDE the kernel (device globals); W and OUT are
//   harness pointers passed as args.  STAGE: 1 = g_X->g_Y1, 2 = g_Y1->out
//   128(m) x 64(o) tile, 256 threads, 8x4 micro, KD = C1 always
// ============================================================
template <int STAGE, int OC>
__global__ __launch_bounds__(256) void k_gemm(const float* __restrict__ W,
                                              float* __restrict__ out)
{
    const float* __restrict__ A = (STAGE == 1) ? g_X : g_Y1;
    float* __restrict__ Y       = (STAGE == 1) ? g_Y1 : out;
    const int KD = C1;

    __shared__ float sA[32][132];
    __shared__ float sB[32][68];

    const int tid = threadIdx.x;
    const int tx  = tid & 15;       // 4 output cols
    const int ty  = tid >> 4;       // 8 output rows
    const size_t m0 = (size_t)blockIdx.x * 128;
    const int    o0 = blockIdx.y * 64;

    float acc[8][4];
#pragma unroll
    for (int r = 0; r < 8; r++)
#pragma unroll
        for (int c = 0; c < 4; c++) acc[r][c] = 0.f;

    for (int k0 = 0; k0 < KD; k0 += 32) {
#pragma unroll
        for (int l = 0; l < 4; l++) {
            int idx = l * 256 + tid;
            int row = idx >> 3;
            int c4  = (idx & 7) * 4;
            float4 v = *(const float4*)(A + (m0 + row) * KD + k0 + c4);
            sA[c4 + 0][row] = v.x; sA[c4 + 1][row] = v.y;
            sA[c4 + 2][row] = v.z; sA[c4 + 3][row] = v.w;
        }
#pragma unroll
        for (int l = 0; l < 2; l++) {
            int idx = l * 256 + tid;
            int row = idx >> 3;
            int c4  = (idx & 7) * 4;
            float4 v = *(const float4*)(W + (size_t)(o0 + row) * KD + k0 + c4);
            sB[c4 + 0][row] = v.x; sB[c4 + 1][row] = v.y;
            sB[c4 + 2][row] = v.z; sB[c4 + 3][row] = v.w;
        }
        __syncthreads();
#pragma unroll
        for (int kk = 0; kk < 32; kk++) {
            float a[8], b[4];
            *(float4*)&a[0] = *(const float4*)&sA[kk][ty * 8];
            *(float4*)&a[4] = *(const float4*)&sA[kk][ty * 8 + 4];
            *(float4*)&b[0] = *(const float4*)&sB[kk][tx * 4];
#pragma unroll
            for (int r = 0; r < 8; r++)
#pragma unroll
                for (int c = 0; c < 4; c++) acc[r][c] += a[r] * b[c];
        }
        __syncthreads();
    }
#pragma unroll
    for (int r = 0; r < 8; r++) {
        float* dst = Y + (m0 + ty * 8 + r) * OC + o0 + tx * 4;
        *(float4*)dst = *(float4*)&acc[r][0];
    }
}

// ============================================================
// stats: per-block partial sum / sumsq per channel (fp64, deterministic)
//   STAGE 1: reads g_Y1 (C1 chans);  STAGE 2: reads `ext` (C2 chans)
// ============================================================
template <int STAGE, int C>
__global__ void k_stats(const float* __restrict__ ext, int rpb)
{
    const float* __restrict__ Y = (STAGE == 1) ? g_Y1 : ext;
    const int c  = threadIdx.x;
    const size_t r0 = (size_t)blockIdx.x * rpb;
    double s = 0.0, q = 0.0;
    for (int r = 0; r < rpb; r++) {
        double v = (double)Y[(r0 + r) * C + c];
        s += v;
        q += v * v;
    }
    g_partd[blockIdx.x * (2 * C) + c]     = s;
    g_partd[blockIdx.x * (2 * C) + C + c] = q;
}

template <int C, int NBLK>
__global__ void k_finalize(const float* __restrict__ g, const float* __restrict__ bb,
                           int aoff)
{
    const int c = threadIdx.x;
    double s = 0.0, q = 0.0;
    for (int i = 0; i < NBLK; i++) {
        s += g_partd[i * (2 * C) + c];
        q += g_partd[i * (2 * C) + C + c];
    }
    const double invM = 1.0 / (double)MTOT;
    double mean = s * invM;
    double var  = q * invM - mean * mean;
    float a = (float)((double)g[c] / sqrt(var + 1e-5));
    g_ab[aoff + c]     = a;
    g_ab[aoff + C + c] = (float)((double)bb[c] - mean * (double)a);
}

// ============================================================
// elementwise BN + LReLU in place: Y = lrelu(a[c]*Y + cc[c])
//   STAGE 1: g_Y1 (C1);  STAGE 2: ext (C2)
// ============================================================
template <int STAGE, int C>
__global__ __launch_bounds__(256) void k_bn_act(float* __restrict__ ext, int aoff)
{
    float* __restrict__ Y = (STAGE == 1) ? g_Y1 : ext;
    size_t i4 = (size_t)blockIdx.x * blockDim.x + threadIdx.x;  // float4 index
    int c4 = (int)(i4 & (C / 4 - 1)) * 4;
    float4 v  = ((float4*)Y)[i4];
    float4 av = *(const float4*)&g_ab[aoff + c4];
    float4 cv = *(const float4*)&g_ab[aoff + C + c4];
    v.x = lrelu(fmaf(av.x, v.x, cv.x));
    v.y = lrelu(fmaf(av.y, v.y, cv.y));
    v.z = lrelu(fmaf(av.z, v.z, cv.z));
    v.w = lrelu(fmaf(av.w, v.w, cv.w));
    ((float4*)Y)[i4] = v;
}

// ============================================================
extern "C" void kernel_launch(void* const* d_in, const int* in_sizes, int n_in,
                              void* d_out, int out_size)
{
    (void)in_sizes; (void)n_in; (void)out_size;
    const float* E0 = (const float*)d_in[0];   // distribution_edge
    const float* E1 = (const float*)d_in[1];   // instance_edge
    const float* P  = (const float*)d_in[2];   // point_node
    const float* W1 = (const float*)d_in[3];
    const float* g1 = (const float*)d_in[4];
    const float* b1 = (const float*)d_in[5];
    const float* W2 = (const float*)d_in[6];
    const float* g2 = (const float*)d_in[7];
    const float* b2 = (const float*)d_in[8];
    float* out = (float*)d_out;

    // 0. masked row sums -> g_invS
    k_rowsum<<<dim3(64, MB, 2), 256>>>(E0, E1);

    // 1. normalize-then-GEMM aggregation -> g_X
    k1_aggr<<<dim3(8, MB, 2), 256>>>(E0, E1, P);

    // 2. GEMM1: g_Y1 = g_X @ W1^T
    k_gemm<1, C1><<<dim3(MTOT / 128, C1 / 64), 256>>>(W1, nullptr);

    // 3. BN1 stats (fp64, deterministic), then BN1+LReLU in place on g_Y1
    k_stats<1, C1><<<256, C1>>>(nullptr, MTOT / 256);
    k_finalize<C1, 256><<<1, C1>>>(g1, b1, 0);
    k_bn_act<1, C1><<<32768, 256>>>(nullptr, 0);

    // 4. GEMM2: out = g_Y1 @ W2^T
    k_gemm<2, C2><<<dim3(MTOT / 128, C2 / 64), 256>>>(W2, out);

    // 5. BN2 stats, then BN2+LReLU in place on out
    k_stats<2, C2><<<256, C2>>>(out, MTOT / 256);
    k_finalize<C2, 256><<<1, C2>>>(g2, b2, 2 * C1);
    k_bn_act<2, C2><<<16384, 256>>>(out, 2 * C1);
}

// round 6
// speedup vs baseline: 1.5675x; 1.5675x over previous
#include <cuda_runtime.h>
#include <cuda_bf16.h>
#include <cstdint>

// Problem constants
#define MB   256
#define NN   512
#define DD   128
#define C1   256
#define C2   128
#define MTOT (MB * NN)

// ---------------- scratch ----------------
__device__ float  g_X[(size_t)MTOT * C1];
__device__ float  g_Y1[(size_t)MTOT * C1];
__device__ double g_partd[512 * 2 * C1];
__device__ float  g_ab[2 * C1 + 2 * C2];

__device__ __forceinline__ float lrelu(float y) { return y >= 0.f ? y : 0.01f * y; }

// ---------------- bf16 split helpers ----------------
__device__ __forceinline__ void bsplit(float x, uint16_t& h, uint16_t& l) {
    __nv_bfloat16 hb = __float2bfloat16(x);
    float r = x - __bfloat162float(hb);
    __nv_bfloat16 lb = __float2bfloat16(r);
    h = __bfloat16_as_ushort(hb);
    l = __bfloat16_as_ushort(lb);
}
__device__ __forceinline__ uint32_t pk(uint16_t a, uint16_t b) {
    return (uint32_t)a | ((uint32_t)b << 16);
}
__device__ __forceinline__ float upsum(uint32_t u) {   // sum of the 2 packed bf16
    __nv_bfloat162 t = *reinterpret_cast<__nv_bfloat162*>(&u);
    return __bfloat162float(t.x) + __bfloat162float(t.y);
}

// m16n8k16 row.col bf16 -> f32 accumulate
__device__ __forceinline__ void mma16816(float* c, const uint32_t* a, const uint32_t* b) {
    asm volatile(
        "mma.sync.aligned.m16n8k16.row.col.f32.bf16.bf16.f32 "
        "{%0,%1,%2,%3}, {%4,%5,%6,%7}, {%8,%9}, {%0,%1,%2,%3};"
        : "+f"(c[0]), "+f"(c[1]), "+f"(c[2]), "+f"(c[3])
        : "r"(a[0]), "r"(a[1]), "r"(a[2]), "r"(a[3]), "r"(b[0]), "r"(b[1]));
}

// ---------------- warp-tile compute over one 32-k chunk ----------------
// shA/shB: [hi/lo][128 rows][20 kpairs(pad)]; 3 passes: hh, hl, lh
// acc[4][4][4]: [mf][nf][c-frag]
__device__ __forceinline__ void compute_chunk(
    const uint32_t (*shA)[128][20], const uint32_t (*shB)[128][20],
    float acc[4][4][4], int wr, int wc, int lane)
{
#pragma unroll
    for (int pass = 0; pass < 3; pass++) {
        const int pa = (pass == 2) ? 1 : 0;
        const int pb = (pass == 1) ? 1 : 0;
#pragma unroll
        for (int ks = 0; ks < 2; ks++) {
            const int kp = ks * 8 + (lane & 3);
            uint32_t af[4][4];
#pragma unroll
            for (int mf = 0; mf < 4; mf++) {
                int r = wr * 64 + mf * 16 + (lane >> 2);
                af[mf][0] = shA[pa][r][kp];
                af[mf][1] = shA[pa][r + 8][kp];
                af[mf][2] = shA[pa][r][kp + 4];
                af[mf][3] = shA[pa][r + 8][kp + 4];
            }
            uint32_t bfr[4][2];
#pragma unroll
            for (int nf = 0; nf < 4; nf++) {
                int n = wc * 32 + nf * 8 + (lane >> 2);
                bfr[nf][0] = shB[pb][n][kp];
                bfr[nf][1] = shB[pb][n][kp + 4];
            }
#pragma unroll
            for (int mf = 0; mf < 4; mf++)
#pragma unroll
                for (int nf = 0; nf < 4; nf++)
                    mma16816(acc[mf][nf], af[mf], bfr[nf]);
        }
    }
}

// ============================================================
// K1: edge aggregation.  CTA: 128 E-rows x 128 D-cols, K=NN=512.
//   A = masked E (bf16 hi/lo), B = P^T.  Row sums computed in-kernel
//   from the masked tiles (deterministic), epilogue scales by 1/rs.
//   grid (4, MB, 2), 256 threads.
// ============================================================
__global__ __launch_bounds__(256) void k1_mma(
    const float* __restrict__ E0, const float* __restrict__ E1,
    const float* __restrict__ P)
{
    __shared__ uint32_t shA[2][128][20];
    __shared__ uint32_t shB[2][128][20];
    __shared__ float sPart[256];
    __shared__ float sInv[128];

    const int tid  = threadIdx.x;
    const int lane = tid & 31;
    const int wid  = tid >> 5;
    const int wr   = wid & 1;     // m half
    const int wc   = wid >> 1;    // n quarter
    const int b    = blockIdx.y;
    const int ez   = blockIdx.z;
    const int row0 = blockIdx.x * 128;
    const float* __restrict__ E  = (ez ? E1 : E0) + (size_t)b * NN * NN;
    const float* __restrict__ Pb = P + (size_t)b * NN * DD;

    float acc[4][4][4];
#pragma unroll
    for (int i = 0; i < 4; i++)
#pragma unroll
        for (int j = 0; j < 4; j++)
#pragma unroll
            for (int k = 0; k < 4; k++) acc[i][j][k] = 0.f;

    const int myrow  = tid >> 1;          // row for rowsum partial
    const int kbase  = (tid & 1) * 8;     // kpair range for this partial
    float rsum = 0.f;

    for (int it = 0; it < 16; it++) {
        const int k0 = it * 32;
        // A: masked E tile, bf16 split. 128 rows x 16 kpairs, float2/thread
#pragma unroll
        for (int l = 0; l < 8; l++) {
            int idx = l * 256 + tid;
            int r   = idx >> 4;
            int kp  = idx & 15;
            int gk  = k0 + 2 * kp;
            int grow = row0 + r;
            float2 v = *(const float2*)(E + (size_t)grow * NN + gk);
            if (grow == gk)     v.x = 0.f;
            if (grow == gk + 1) v.y = 0.f;
            uint16_t h0, l0, h1, l1;
            bsplit(v.x, h0, l0); bsplit(v.y, h1, l1);
            shA[0][r][kp] = pk(h0, h1);
            shA[1][r][kp] = pk(l0, l1);
        }
        // B: P^T tile.  shB[*][n=d][k=j] = split(P[k0+j][d])
#pragma unroll
        for (int l = 0; l < 16; l++) {
            int idx = l * 256 + tid;
            int n   = idx & 127;
            int kk  = idx >> 7;         // 0..31
            float x = Pb[(size_t)(k0 + kk) * DD + n];
            uint16_t h, lo;
            bsplit(x, h, lo);
            ((uint16_t*)shB[0][n])[kk] = h;
            ((uint16_t*)shB[1][n])[kk] = lo;
        }
        __syncthreads();

        // deterministic masked row-sum (half row per thread)
#pragma unroll
        for (int kp = 0; kp < 8; kp++) {
            rsum += upsum(shA[0][myrow][kbase + kp]);
            rsum += upsum(shA[1][myrow][kbase + kp]);
        }

        compute_chunk(shA, shB, acc, wr, wc, lane);
        __syncthreads();
    }

    sPart[tid] = rsum;
    __syncthreads();
    if (tid < 128)
        sInv[tid] = 1.0f / fmaxf(sPart[2 * tid] + sPart[2 * tid + 1], 1e-12f);
    __syncthreads();

    // epilogue: scale by inv row-sum, store to g_X
#pragma unroll
    for (int mf = 0; mf < 4; mf++) {
        int rl = wr * 64 + mf * 16 + (lane >> 2);
#pragma unroll
        for (int nf = 0; nf < 4; nf++) {
            int col = ez * DD + wc * 32 + nf * 8 + (lane & 3) * 2;
            float i0 = sInv[rl], i1 = sInv[rl + 8];
            float* d0 = g_X + ((size_t)b * NN + row0 + rl) * C1 + col;
            float* d1 = g_X + ((size_t)b * NN + row0 + rl + 8) * C1 + col;
            float2 v0 = { acc[mf][nf][0] * i0, acc[mf][nf][1] * i0 };
            float2 v1 = { acc[mf][nf][2] * i1, acc[mf][nf][3] * i1 };
            *(float2*)d0 = v0;
            *(float2*)d1 = v1;
        }
    }
}

// ============================================================
// GEMM (mma):  Y[m,o] = sum_c A[m,c] * W[o,c],  KD = C1 = 256
//   STAGE 1: g_X -> g_Y1 (grid y=2); STAGE 2: g_Y1 -> out (grid y=1)
// ============================================================
template <int STAGE>
__global__ __launch_bounds__(256) void k_gemm_mma(const float* __restrict__ W,
                                                  float* __restrict__ outExt)
{
    const float* __restrict__ A = (STAGE == 1) ? g_X : g_Y1;
    float* __restrict__ Y       = (STAGE == 1) ? g_Y1 : outExt;
    const int OC = (STAGE == 1) ? C1 : C2;

    __shared__ uint32_t shA[2][128][20];
    __shared__ uint32_t shB[2][128][20];

    const int tid  = threadIdx.x;
    const int lane = tid & 31;
    const int wid  = tid >> 5;
    const int wr   = wid & 1;
    const int wc   = wid >> 1;
    const size_t m0 = (size_t)blockIdx.x * 128;
    const int    o0 = blockIdx.y * 128;

    float acc[4][4][4];
#pragma unroll
    for (int i = 0; i < 4; i++)
#pragma unroll
        for (int j = 0; j < 4; j++)
#pragma unroll
            for (int k = 0; k < 4; k++) acc[i][j][k] = 0.f;

    for (int it = 0; it < 8; it++) {
        const int k0 = it * 32;
#pragma unroll
        for (int l = 0; l < 8; l++) {
            int idx = l * 256 + tid;
            int r   = idx >> 4;
            int kp  = idx & 15;
            float2 v = *(const float2*)(A + (m0 + r) * C1 + k0 + 2 * kp);
            uint16_t h0, l0, h1, l1;
            bsplit(v.x, h0, l0); bsplit(v.y, h1, l1);
            shA[0][r][kp] = pk(h0, h1);
            shA[1][r][kp] = pk(l0, l1);
        }
#pragma unroll
        for (int l = 0; l < 8; l++) {
            int idx = l * 256 + tid;
            int n   = idx >> 4;
            int kp  = idx & 15;
            float2 v = *(const float2*)(W + (size_t)(o0 + n) * C1 + k0 + 2 * kp);
            uint16_t h0, l0, h1, l1;
            bsplit(v.x, h0, l0); bsplit(v.y, h1, l1);
            shB[0][n][kp] = pk(h0, h1);
            shB[1][n][kp] = pk(l0, l1);
        }
        __syncthreads();
        compute_chunk(shA, shB, acc, wr, wc, lane);
        __syncthreads();
    }

#pragma unroll
    for (int mf = 0; mf < 4; mf++) {
        int rl = wr * 64 + mf * 16 + (lane >> 2);
#pragma unroll
        for (int nf = 0; nf < 4; nf++) {
            int col = o0 + wc * 32 + nf * 8 + (lane & 3) * 2;
            float* d0 = Y + (m0 + rl) * OC + col;
            float* d1 = Y + (m0 + rl + 8) * OC + col;
            *(float2*)d0 = { acc[mf][nf][0], acc[mf][nf][1] };
            *(float2*)d1 = { acc[mf][nf][2], acc[mf][nf][3] };
        }
    }
}

// ============================================================
// stats: 512 blocks, 8 independent fp64 chains (deterministic)
// ============================================================
template <int STAGE, int C>
__global__ void k_stats(const float* __restrict__ ext, int rpb)
{
    const float* __restrict__ Y = (STAGE == 1) ? g_Y1 : ext;
    const int c  = threadIdx.x;
    const size_t r0 = (size_t)blockIdx.x * rpb;
    double s[8] = {0, 0, 0, 0, 0, 0, 0, 0};
    double q[8] = {0, 0, 0, 0, 0, 0, 0, 0};
    for (int r = 0; r < rpb; r += 8) {
#pragma unroll
        for (int j = 0; j < 8; j++) {
            double v = (double)Y[(r0 + r + j) * C + c];
            s[j] += v;
            q[j] += v * v;
        }
    }
    double ss = ((s[0] + s[1]) + (s[2] + s[3])) + ((s[4] + s[5]) + (s[6] + s[7]));
    double qq = ((q[0] + q[1]) + (q[2] + q[3])) + ((q[4] + q[5]) + (q[6] + q[7]));
    g_partd[blockIdx.x * (2 * C) + c]     = ss;
    g_partd[blockIdx.x * (2 * C) + C + c] = qq;
}

template <int C, int NBLK>
__global__ void k_finalize(const float* __restrict__ g, const float* __restrict__ bb,
                           int aoff)
{
    const int c = threadIdx.x;
    double s[8] = {0, 0, 0, 0, 0, 0, 0, 0};
    double q[8] = {0, 0, 0, 0, 0, 0, 0, 0};
    for (int i = 0; i < NBLK; i += 8) {
#pragma unroll
        for (int j = 0; j < 8; j++) {
            s[j] += g_partd[(i + j) * (2 * C) + c];
            q[j] += g_partd[(i + j) * (2 * C) + C + c];
        }
    }
    double ss = ((s[0] + s[1]) + (s[2] + s[3])) + ((s[4] + s[5]) + (s[6] + s[7]));
    double qq = ((q[0] + q[1]) + (q[2] + q[3])) + ((q[4] + q[5]) + (q[6] + q[7]));
    const double invM = 1.0 / (double)MTOT;
    double mean = ss * invM;
    double var  = qq * invM - mean * mean;
    float a = (float)((double)g[c] / sqrt(var + 1e-5));
    g_ab[aoff + c]     = a;
    g_ab[aoff + C + c] = (float)((double)bb[c] - mean * (double)a);
}

// ============================================================
// elementwise BN + LReLU in place
// ============================================================
template <int STAGE, int C>
__global__ __launch_bounds__(256) void k_bn_act(float* __restrict__ ext, int aoff)
{
    float* __restrict__ Y = (STAGE == 1) ? g_Y1 : ext;
    size_t i4 = (size_t)blockIdx.x * blockDim.x + threadIdx.x;
    int c4 = (int)(i4 & (C / 4 - 1)) * 4;
    float4 v  = ((float4*)Y)[i4];
    float4 av = *(const float4*)&g_ab[aoff + c4];
    float4 cv = *(const float4*)&g_ab[aoff + C + c4];
    v.x = lrelu(fmaf(av.x, v.x, cv.x));
    v.y = lrelu(fmaf(av.y, v.y, cv.y));
    v.z = lrelu(fmaf(av.z, v.z, cv.z));
    v.w = lrelu(fmaf(av.w, v.w, cv.w));
    ((float4*)Y)[i4] = v;
}

// ============================================================
extern "C" void kernel_launch(void* const* d_in, const int* in_sizes, int n_in,
                              void* d_out, int out_size)
{
    (void)in_sizes; (void)n_in; (void)out_size;
    const float* E0 = (const float*)d_in[0];
    const float* E1 = (const float*)d_in[1];
    const float* P  = (const float*)d_in[2];
    const float* W1 = (const float*)d_in[3];
    const float* g1 = (const float*)d_in[4];
    const float* b1 = (const float*)d_in[5];
    const float* W2 = (const float*)d_in[6];
    const float* g2 = (const float*)d_in[7];
    const float* b2 = (const float*)d_in[8];
    float* out = (float*)d_out;

    // 1. edge aggregation + fused row-sum + L1 normalize -> g_X
    k1_mma<<<dim3(4, MB, 2), 256>>>(E0, E1, P);

    // 2. GEMM1: g_Y1 = g_X @ W1^T
    k_gemm_mma<1><<<dim3(MTOT / 128, 2), 256>>>(W1, nullptr);

    // 3. BN1 stats + in-place BN1+LReLU
    k_stats<1, C1><<<512, C1>>>(nullptr, MTOT / 512);
    k_finalize<C1, 512><<<1, C1>>>(g1, b1, 0);
    k_bn_act<1, C1><<<32768, 256>>>(nullptr, 0);

    // 4. GEMM2: out = g_Y1 @ W2^T
    k_gemm_mma<2><<<dim3(MTOT / 128, 1), 256>>>(W2, out);

    // 5. BN2 stats + in-place BN2+LReLU
    k_stats<2, C2><<<512, C2>>>(out, MTOT / 512);
    k_finalize<C2, 512><<<1, C2>>>(g2, b2, 2 * C1);
    k_bn_act<2, C2><<<16384, 256>>>(out, 2 * C1);
}

// round 7
// speedup vs baseline: 1.9546x; 1.2470x over previous
#include <cuda_runtime.h>
#include <cuda_bf16.h>
#include <cstdint>

// Problem constants
#define MB   256
#define NN   512
#define DD   128
#define C1   256
#define C2   128
#define MTOT (MB * NN)

// ---------------- scratch ----------------
__device__ uint32_t g_Pt[(size_t)MB * 2 * DD * (NN / 2)];   // P^T split kpairs  (67MB)
__device__ uint32_t g_Xs[2 * (size_t)MTOT * (C1 / 2)];      // X split kpairs    (134MB)
__device__ float    g_Y1[(size_t)MTOT * C1];                // raw GEMM1 out     (134MB)
__device__ uint32_t g_W1s[2 * C1 * (C1 / 2)];
__device__ uint32_t g_W2s[2 * C2 * (C1 / 2)];
__device__ double   g_partd[512 * 2 * C1];
__device__ float    g_ab[2 * C1 + 2 * C2];

__device__ __forceinline__ float lrelu(float y) { return y >= 0.f ? y : 0.01f * y; }

// ---------------- bf16 split helpers ----------------
__device__ __forceinline__ void bsplit(float x, uint16_t& h, uint16_t& l) {
    __nv_bfloat16 hb = __float2bfloat16(x);
    float r = x - __bfloat162float(hb);
    __nv_bfloat16 lb = __float2bfloat16(r);
    h = __bfloat16_as_ushort(hb);
    l = __bfloat16_as_ushort(lb);
}
__device__ __forceinline__ uint32_t pk(uint16_t a, uint16_t b) {
    return (uint32_t)a | ((uint32_t)b << 16);
}
__device__ __forceinline__ float upsum(uint32_t u) {
    __nv_bfloat162 t = *reinterpret_cast<__nv_bfloat162*>(&u);
    return __bfloat162float(t.x) + __bfloat162float(t.y);
}

__device__ __forceinline__ void mma16816(float* c, const uint32_t* a, const uint32_t* b) {
    asm volatile(
        "mma.sync.aligned.m16n8k16.row.col.f32.bf16.bf16.f32 "
        "{%0,%1,%2,%3}, {%4,%5,%6,%7}, {%8,%9}, {%0,%1,%2,%3};"
        : "+f"(c[0]), "+f"(c[1]), "+f"(c[2]), "+f"(c[3])
        : "r"(a[0]), "r"(a[1]), "r"(a[2]), "r"(a[3]), "r"(b[0]), "r"(b[1]));
}

// ---------------- warp-tile compute over one 32-k chunk ----------------
__device__ __forceinline__ void compute_chunk(
    const uint32_t (*shA)[128][20], const uint32_t (*shB)[128][20],
    float acc[4][4][4], int wr, int wc, int lane)
{
#pragma unroll
    for (int pass = 0; pass < 3; pass++) {
        const int pa = (pass == 2) ? 1 : 0;
        const int pb = (pass == 1) ? 1 : 0;
#pragma unroll
        for (int ks = 0; ks < 2; ks++) {
            const int kp = ks * 8 + (lane & 3);
            uint32_t af[4][4];
#pragma unroll
            for (int mf = 0; mf < 4; mf++) {
                int r = wr * 64 + mf * 16 + (lane >> 2);
                af[mf][0] = shA[pa][r][kp];
                af[mf][1] = shA[pa][r + 8][kp];
                af[mf][2] = shA[pa][r][kp + 4];
                af[mf][3] = shA[pa][r + 8][kp + 4];
            }
            uint32_t bfr[4][2];
#pragma unroll
            for (int nf = 0; nf < 4; nf++) {
                int n = wc * 32 + nf * 8 + (lane >> 2);
                bfr[nf][0] = shB[pb][n][kp];
                bfr[nf][1] = shB[pb][n][kp + 4];
            }
#pragma unroll
            for (int mf = 0; mf < 4; mf++)
#pragma unroll
                for (int nf = 0; nf < 4; nf++)
                    mma16816(acc[mf][nf], af[mf], bfr[nf]);
        }
    }
}

// ============================================================
// kP: P -> transposed split planes g_Pt[b][pa][d][kp]
//   block = (b, kt): 64 k-rows x 128 d, smem transpose
// ============================================================
__global__ __launch_bounds__(256) void kP_split(const float* __restrict__ P)
{
    __shared__ uint16_t sH16[128][66];
    __shared__ uint16_t sL16[128][66];

    const int tid = threadIdx.x;
    const int b   = blockIdx.x;
    const int kt  = blockIdx.y;            // 0..7, 64 k each
    const float* __restrict__ Pb = P + ((size_t)b * NN + kt * 64) * DD;

    // load 64k x 128d as float2 over d, split, transpose into smem
#pragma unroll
    for (int l = 0; l < 16; l++) {
        int idx = l * 256 + tid;           // 0..4095
        int k   = idx >> 6;                // 0..63
        int d2  = idx & 63;                // float2 over d
        float2 v = *(const float2*)(Pb + (size_t)k * DD + 2 * d2);
        uint16_t h0, l0, h1, l1;
        bsplit(v.x, h0, l0); bsplit(v.y, h1, l1);
        sH16[2 * d2][k]     = h0; sL16[2 * d2][k]     = l0;
        sH16[2 * d2 + 1][k] = h1; sL16[2 * d2 + 1][k] = l1;
    }
    __syncthreads();

    // write coalesced over kp (32 kpairs per block)
#pragma unroll
    for (int l = 0; l < 32; l++) {
        int idx = l * 256 + tid;           // 0..8191
        int pa  = idx >> 12;
        int rem = idx & 4095;
        int d   = rem >> 5;
        int kp  = rem & 31;
        const uint16_t* s = pa ? &sL16[d][0] : &sH16[d][0];
        uint32_t v = pk(s[2 * kp], s[2 * kp + 1]);
        g_Pt[(((size_t)b * 2 + pa) * DD + d) * (NN / 2) + kt * 32 + kp] = v;
    }
}

// ============================================================
// kW: weight split (WS=1: W1 256x256, WS=2: W2 128x256)
// ============================================================
template <int WS>
__global__ __launch_bounds__(256) void kW_split(const float* __restrict__ W)
{
    uint32_t* dst = (WS == 1) ? g_W1s : g_W2s;
    const int OC  = (WS == 1) ? C1 : C2;
    int idx = blockIdx.x * 256 + threadIdx.x;    // (o, kp)
    int o   = idx >> 7;
    int kp  = idx & 127;
    if (o >= OC) return;
    float2 v = *(const float2*)(W + (size_t)o * C1 + 2 * kp);
    uint16_t h0, l0, h1, l1;
    bsplit(v.x, h0, l0); bsplit(v.y, h1, l1);
    dst[(size_t)o * 128 + kp]                      = pk(h0, h1);
    dst[(size_t)OC * 128 + (size_t)o * 128 + kp]   = pk(l0, l1);
}

// ============================================================
// K1: edge aggregation.  CTA: 128 E-rows x 128 D-cols, K=512.
//   A = masked E (split in-kernel, float4 loads), B = g_Pt (precomputed).
//   In-kernel deterministic masked row-sum; epilogue scales and stores
//   g_Xs as split u32 planes.  grid (4, MB, 2), 256 threads.
// ============================================================
__global__ __launch_bounds__(256) void k1_mma(
    const float* __restrict__ E0, const float* __restrict__ E1)
{
    __shared__ uint32_t shA[2][128][20];
    __shared__ uint32_t shB[2][128][20];
    __shared__ float sPart[256];
    __shared__ float sInv[128];

    const int tid  = threadIdx.x;
    const int lane = tid & 31;
    const int wid  = tid >> 5;
    const int wr   = wid & 1;
    const int wc   = wid >> 1;
    const int b    = blockIdx.y;
    const int ez   = blockIdx.z;
    const int row0 = blockIdx.x * 128;
    const float* __restrict__ E = (ez ? E1 : E0) + (size_t)b * NN * NN;
    const uint32_t* __restrict__ Pt = g_Pt + (size_t)b * 2 * DD * (NN / 2);

    float acc[4][4][4];
#pragma unroll
    for (int i = 0; i < 4; i++)
#pragma unroll
        for (int j = 0; j < 4; j++)
#pragma unroll
            for (int k = 0; k < 4; k++) acc[i][j][k] = 0.f;

    const int myrow = tid >> 1;
    const int kbase = (tid & 1) * 8;
    float rsum = 0.f;

    for (int it = 0; it < 16; it++) {
        const int k0 = it * 32;
        // A: masked E tile via float4; 128r x 8 quads
#pragma unroll
        for (int l = 0; l < 4; l++) {
            int idx = l * 256 + tid;       // 0..1023
            int r   = idx >> 3;
            int q   = idx & 7;
            int gk  = k0 + q * 4;
            int grow = row0 + r;
            float4 v = *(const float4*)(E + (size_t)grow * NN + gk);
            if (grow == gk)     v.x = 0.f;
            if (grow == gk + 1) v.y = 0.f;
            if (grow == gk + 2) v.z = 0.f;
            if (grow == gk + 3) v.w = 0.f;
            uint16_t h0, l0, h1, l1, h2, l2, h3, l3;
            bsplit(v.x, h0, l0); bsplit(v.y, h1, l1);
            bsplit(v.z, h2, l2); bsplit(v.w, h3, l3);
            shA[0][r][2 * q]     = pk(h0, h1);
            shA[0][r][2 * q + 1] = pk(h2, h3);
            shA[1][r][2 * q]     = pk(l0, l1);
            shA[1][r][2 * q + 1] = pk(l2, l3);
        }
        // B: direct u32 copies from g_Pt
#pragma unroll
        for (int l = 0; l < 16; l++) {
            int idx = l * 256 + tid;       // 0..4095
            int pb  = idx >> 11;
            int rem = idx & 2047;
            int n   = rem >> 4;
            int kpl = rem & 15;
            shB[pb][n][kpl] = Pt[((size_t)pb * DD + n) * (NN / 2) + (k0 >> 1) + kpl];
        }
        __syncthreads();

#pragma unroll
        for (int kp = 0; kp < 8; kp++) {
            rsum += upsum(shA[0][myrow][kbase + kp]);
            rsum += upsum(shA[1][myrow][kbase + kp]);
        }

        compute_chunk(shA, shB, acc, wr, wc, lane);
        __syncthreads();
    }

    sPart[tid] = rsum;
    __syncthreads();
    if (tid < 128)
        sInv[tid] = 1.0f / fmaxf(sPart[2 * tid] + sPart[2 * tid + 1], 1e-12f);
    __syncthreads();

    // epilogue: scale, split, store both planes of g_Xs
#pragma unroll
    for (int mf = 0; mf < 4; mf++) {
        int rl = wr * 64 + mf * 16 + (lane >> 2);
#pragma unroll
        for (int nf = 0; nf < 4; nf++) {
            int kpo = ez * 64 + wc * 16 + nf * 4 + (lane & 3);   // kpair in [0,128)
            float i0 = sInv[rl], i1 = sInv[rl + 8];
            size_t m0r = (size_t)b * NN + row0 + rl;
            size_t m1r = m0r + 8;
            uint16_t h0, l0, h1, l1;
            bsplit(acc[mf][nf][0] * i0, h0, l0);
            bsplit(acc[mf][nf][1] * i0, h1, l1);
            g_Xs[m0r * 128 + kpo]                        = pk(h0, h1);
            g_Xs[(size_t)MTOT * 128 + m0r * 128 + kpo]   = pk(l0, l1);
            bsplit(acc[mf][nf][2] * i1, h0, l0);
            bsplit(acc[mf][nf][3] * i1, h1, l1);
            g_Xs[m1r * 128 + kpo]                        = pk(h0, h1);
            g_Xs[(size_t)MTOT * 128 + m1r * 128 + kpo]   = pk(l0, l1);
        }
    }
}

// ============================================================
// GEMM (mma):  Y[m,o] = sum_c A[m,c] * W[o,c],  KD = C1 = 256
//   STAGE 1: A = g_Xs (pure copies) -> g_Y1
//   STAGE 2: A = bn1+lrelu(g_Y1) split on load -> out
// ============================================================
template <int STAGE>
__global__ __launch_bounds__(256) void k_gemm_mma(float* __restrict__ outExt)
{
    const int OC = (STAGE == 1) ? C1 : C2;
    float* __restrict__ Y = (STAGE == 1) ? g_Y1 : outExt;
    const uint32_t* __restrict__ Ws = (STAGE == 1) ? g_W1s : g_W2s;

    __shared__ uint32_t shA[2][128][20];
    __shared__ uint32_t shB[2][128][20];
    __shared__ float sBNa[C1], sBNc[C1];

    const int tid  = threadIdx.x;
    const int lane = tid & 31;
    const int wid  = tid >> 5;
    const int wr   = wid & 1;
    const int wc   = wid >> 1;
    const size_t m0 = (size_t)blockIdx.x * 128;
    const int    o0 = blockIdx.y * 128;

    if (STAGE == 2) {
        sBNa[tid] = g_ab[tid];
        sBNc[tid] = g_ab[C1 + tid];
        __syncthreads();
    }

    float acc[4][4][4];
#pragma unroll
    for (int i = 0; i < 4; i++)
#pragma unroll
        for (int j = 0; j < 4; j++)
#pragma unroll
            for (int k = 0; k < 4; k++) acc[i][j][k] = 0.f;

    for (int it = 0; it < 8; it++) {
        const int k0 = it * 32;
        if (STAGE == 1) {
#pragma unroll
            for (int l = 0; l < 16; l++) {
                int idx = l * 256 + tid;
                int pa  = idx >> 11;
                int rem = idx & 2047;
                int r   = rem >> 4;
                int kpl = rem & 15;
                shA[pa][r][kpl] =
                    g_Xs[(size_t)pa * MTOT * 128 + (m0 + r) * 128 + (k0 >> 1) + kpl];
            }
        } else {
#pragma unroll
            for (int l = 0; l < 8; l++) {
                int idx = l * 256 + tid;
                int r   = idx >> 4;
                int kp  = idx & 15;
                int ch  = k0 + 2 * kp;
                float2 v = *(const float2*)(g_Y1 + (m0 + r) * C1 + ch);
                v.x = lrelu(fmaf(sBNa[ch],     v.x, sBNc[ch]));
                v.y = lrelu(fmaf(sBNa[ch + 1], v.y, sBNc[ch + 1]));
                uint16_t h0, l0, h1, l1;
                bsplit(v.x, h0, l0); bsplit(v.y, h1, l1);
                shA[0][r][kp] = pk(h0, h1);
                shA[1][r][kp] = pk(l0, l1);
            }
        }
#pragma unroll
        for (int l = 0; l < 16; l++) {
            int idx = l * 256 + tid;
            int pb  = idx >> 11;
            int rem = idx & 2047;
            int n   = rem >> 4;
            int kpl = rem & 15;
            shB[pb][n][kpl] =
                Ws[(size_t)pb * OC * 128 + (size_t)(o0 + n) * 128 + (k0 >> 1) + kpl];
        }
        __syncthreads();
        compute_chunk(shA, shB, acc, wr, wc, lane);
        __syncthreads();
    }

#pragma unroll
    for (int mf = 0; mf < 4; mf++) {
        int rl = wr * 64 + mf * 16 + (lane >> 2);
#pragma unroll
        for (int nf = 0; nf < 4; nf++) {
            int col = o0 + wc * 32 + nf * 8 + (lane & 3) * 2;
            float* d0 = Y + (m0 + rl) * OC + col;
            float* d1 = Y + (m0 + rl + 8) * OC + col;
            *(float2*)d0 = { acc[mf][nf][0], acc[mf][nf][1] };
            *(float2*)d1 = { acc[mf][nf][2], acc[mf][nf][3] };
        }
    }
}

// ============================================================
// stats: 512 blocks, 8 independent fp64 chains (deterministic)
// ============================================================
template <int STAGE, int C>
__global__ void k_stats(const float* __restrict__ ext, int rpb)
{
    const float* __restrict__ Y = (STAGE == 1) ? g_Y1 : ext;
    const int c  = threadIdx.x;
    const size_t r0 = (size_t)blockIdx.x * rpb;
    double s[8] = {0, 0, 0, 0, 0, 0, 0, 0};
    double q[8] = {0, 0, 0, 0, 0, 0, 0, 0};
    for (int r = 0; r < rpb; r += 8) {
#pragma unroll
        for (int j = 0; j < 8; j++) {
            double v = (double)Y[(r0 + r + j) * C + c];
            s[j] += v;
            q[j] += v * v;
        }
    }
    double ss = ((s[0] + s[1]) + (s[2] + s[3])) + ((s[4] + s[5]) + (s[6] + s[7]));
    double qq = ((q[0] + q[1]) + (q[2] + q[3])) + ((q[4] + q[5]) + (q[6] + q[7]));
    g_partd[blockIdx.x * (2 * C) + c]     = ss;
    g_partd[blockIdx.x * (2 * C) + C + c] = qq;
}

// ============================================================
// finalize: one block per channel, smem tree reduction (deterministic)
// ============================================================
template <int C, int NBLK>
__global__ __launch_bounds__(256) void k_finalize(
    const float* __restrict__ g, const float* __restrict__ bb, int aoff)
{
    __shared__ double ss[256], sq[256];
    const int c   = blockIdx.x;
    const int tid = threadIdx.x;
    double s = 0.0, q = 0.0;
    for (int i = tid; i < NBLK; i += 256) {
        s += g_partd[(size_t)i * (2 * C) + c];
        q += g_partd[(size_t)i * (2 * C) + C + c];
    }
    ss[tid] = s; sq[tid] = q;
    __syncthreads();
    for (int off = 128; off > 0; off >>= 1) {
        if (tid < off) { ss[tid] += ss[tid + off]; sq[tid] += sq[tid + off]; }
        __syncthreads();
    }
    if (tid == 0) {
        const double invM = 1.0 / (double)MTOT;
        double mean = ss[0] * invM;
        double var  = sq[0] * invM - mean * mean;
        float a = (float)((double)g[c] / sqrt(var + 1e-5));
        g_ab[aoff + c]     = a;
        g_ab[aoff + C + c] = (float)((double)bb[c] - mean * (double)a);
    }
}

// ============================================================
// elementwise BN + LReLU in place (stage 2 / final output only)
// ============================================================
__global__ __launch_bounds__(256) void k_bn_act2(float* __restrict__ Y)
{
    size_t i4 = (size_t)blockIdx.x * blockDim.x + threadIdx.x;
    int c4 = (int)(i4 & (C2 / 4 - 1)) * 4;
    float4 v  = ((float4*)Y)[i4];
    float4 av = *(const float4*)&g_ab[2 * C1 + c4];
    float4 cv = *(const float4*)&g_ab[2 * C1 + C2 + c4];
    v.x = lrelu(fmaf(av.x, v.x, cv.x));
    v.y = lrelu(fmaf(av.y, v.y, cv.y));
    v.z = lrelu(fmaf(av.z, v.z, cv.z));
    v.w = lrelu(fmaf(av.w, v.w, cv.w));
    ((float4*)Y)[i4] = v;
}

// ============================================================
extern "C" void kernel_launch(void* const* d_in, const int* in_sizes, int n_in,
                              void* d_out, int out_size)
{
    (void)in_sizes; (void)n_in; (void)out_size;
    const float* E0 = (const float*)d_in[0];
    const float* E1 = (const float*)d_in[1];
    const float* P  = (const float*)d_in[2];
    const float* W1 = (const float*)d_in[3];
    const float* g1 = (const float*)d_in[4];
    const float* b1 = (const float*)d_in[5];
    const float* W2 = (const float*)d_in[6];
    const float* g2 = (const float*)d_in[7];
    const float* b2 = (const float*)d_in[8];
    float* out = (float*)d_out;

    // 0. one-time conversions
    kP_split<<<dim3(MB, 8), 256>>>(P);
    kW_split<1><<<(C1 * 128) / 256, 256>>>(W1);
    kW_split<2><<<(C2 * 128) / 256, 256>>>(W2);

    // 1. edge aggregation + fused row-sum + L1 normalize -> g_Xs (split)
    k1_mma<<<dim3(4, MB, 2), 256>>>(E0, E1);

    // 2. GEMM1: g_Y1 = X @ W1^T   (pure-copy A tiles)
    k_gemm_mma<1><<<dim3(MTOT / 128, 2), 256>>>(nullptr);

    // 3. BN1 stats + parallel finalize (BN1+LReLU fused into GEMM2 load)
    k_stats<1, C1><<<512, C1>>>(nullptr, MTOT / 512);
    k_finalize<C1, 512><<<C1, 256>>>(g1, b1, 0);

    // 4. GEMM2: out = lrelu(bn1(g_Y1)) @ W2^T
    k_gemm_mma<2><<<dim3(MTOT / 128, 1), 256>>>(out);

    // 5. BN2 stats + finalize + in-place BN2+LReLU
    k_stats<2, C2><<<512, C2>>>(out, MTOT / 512);
    k_finalize<C2, 512><<<C2, 256>>>(g2, b2, 2 * C1);
    k_bn_act2<<<16384, 256>>>(out);
}

// round 8
// speedup vs baseline: 2.3487x; 1.2016x over previous
#include <cuda_runtime.h>
#include <cuda_bf16.h>
#include <cstdint>

// Problem constants
#define MB   256
#define NN   512
#define DD   128
#define C1   256
#define C2   128
#define MTOT (MB * NN)

// ---------------- scratch ----------------
__device__ uint32_t g_Pt[(size_t)MB * 2 * DD * (NN / 2)];
__device__ uint32_t g_Xs[2 * (size_t)MTOT * (C1 / 2)];
__device__ float    g_Y1[(size_t)MTOT * C1];
__device__ uint32_t g_W1s[2 * C1 * (C1 / 2)];
__device__ uint32_t g_W2s[2 * C2 * (C1 / 2)];
__device__ double   g_partd[512 * 2 * C1];
__device__ float    g_ab[2 * C1 + 2 * C2];

__device__ __forceinline__ float lrelu(float y) { return y >= 0.f ? y : 0.01f * y; }

// ---------------- helpers ----------------
__device__ __forceinline__ void bsplit(float x, uint16_t& h, uint16_t& l) {
    __nv_bfloat16 hb = __float2bfloat16(x);
    float r = x - __bfloat162float(hb);
    __nv_bfloat16 lb = __float2bfloat16(r);
    h = __bfloat16_as_ushort(hb);
    l = __bfloat16_as_ushort(lb);
}
__device__ __forceinline__ uint32_t pk(uint16_t a, uint16_t b) {
    return (uint32_t)a | ((uint32_t)b << 16);
}
__device__ __forceinline__ uint32_t smem_u32(const void* p) {
    uint32_t a;
    asm("{ .reg .u64 t; cvta.to.shared.u64 t, %1; cvt.u32.u64 %0, t; }" : "=r"(a) : "l"(p));
    return a;
}
__device__ __forceinline__ void cpasync16(uint32_t saddr, const void* g) {
    asm volatile("cp.async.cg.shared.global [%0], [%1], 16;" :: "r"(saddr), "l"(g));
}
#define CP_COMMIT() asm volatile("cp.async.commit_group;" ::: "memory")
#define CP_WAIT0()  asm volatile("cp.async.wait_group 0;" ::: "memory")

__device__ __forceinline__ void mma16816(float* c, const uint32_t* a, const uint32_t* b) {
    asm volatile(
        "mma.sync.aligned.m16n8k16.row.col.f32.bf16.bf16.f32 "
        "{%0,%1,%2,%3}, {%4,%5,%6,%7}, {%8,%9}, {%0,%1,%2,%3};"
        : "+f"(c[0]), "+f"(c[1]), "+f"(c[2]), "+f"(c[3])
        : "r"(a[0]), "r"(a[1]), "r"(a[2]), "r"(a[3]), "r"(b[0]), "r"(b[1]));
}

// ---------------- warp-tile compute over one 32-k chunk ----------------
__device__ __forceinline__ void compute_chunk(
    const uint32_t (*shA)[128][20], const uint32_t (*shB)[128][20],
    float acc[4][4][4], int wr, int wc, int lane)
{
#pragma unroll
    for (int pass = 0; pass < 3; pass++) {
        const int pa = (pass == 2) ? 1 : 0;
        const int pb = (pass == 1) ? 1 : 0;
#pragma unroll
        for (int ks = 0; ks < 2; ks++) {
            const int kp = ks * 8 + (lane & 3);
            uint32_t af[4][4];
#pragma unroll
            for (int mf = 0; mf < 4; mf++) {
                int r = wr * 64 + mf * 16 + (lane >> 2);
                af[mf][0] = shA[pa][r][kp];
                af[mf][1] = shA[pa][r + 8][kp];
                af[mf][2] = shA[pa][r][kp + 4];
                af[mf][3] = shA[pa][r + 8][kp + 4];
            }
            uint32_t bfr[4][2];
#pragma unroll
            for (int nf = 0; nf < 4; nf++) {
                int n = wc * 32 + nf * 8 + (lane >> 2);
                bfr[nf][0] = shB[pb][n][kp];
                bfr[nf][1] = shB[pb][n][kp + 4];
            }
#pragma unroll
            for (int mf = 0; mf < 4; mf++)
#pragma unroll
                for (int nf = 0; nf < 4; nf++)
                    mma16816(acc[mf][nf], af[mf], bfr[nf]);
        }
    }
}

// ============================================================
// kP: P -> transposed split planes g_Pt[b][pa][d][kp]
// ============================================================
__global__ __launch_bounds__(256) void kP_split(const float* __restrict__ P)
{
    __shared__ uint16_t sH16[128][66];
    __shared__ uint16_t sL16[128][66];

    const int tid = threadIdx.x;
    const int b   = blockIdx.x;
    const int kt  = blockIdx.y;
    const float* __restrict__ Pb = P + ((size_t)b * NN + kt * 64) * DD;

#pragma unroll
    for (int l = 0; l < 16; l++) {
        int idx = l * 256 + tid;
        int k   = idx >> 6;
        int d2  = idx & 63;
        float2 v = *(const float2*)(Pb + (size_t)k * DD + 2 * d2);
        uint16_t h0, l0, h1, l1;
        bsplit(v.x, h0, l0); bsplit(v.y, h1, l1);
        sH16[2 * d2][k]     = h0; sL16[2 * d2][k]     = l0;
        sH16[2 * d2 + 1][k] = h1; sL16[2 * d2 + 1][k] = l1;
    }
    __syncthreads();
#pragma unroll
    for (int l = 0; l < 32; l++) {
        int idx = l * 256 + tid;
        int pa  = idx >> 12;
        int rem = idx & 4095;
        int d   = rem >> 5;
        int kp  = rem & 31;
        const uint16_t* s = pa ? &sL16[d][0] : &sH16[d][0];
        g_Pt[(((size_t)b * 2 + pa) * DD + d) * (NN / 2) + kt * 32 + kp] =
            pk(s[2 * kp], s[2 * kp + 1]);
    }
}

// ============================================================
// kW: weight split
// ============================================================
template <int WS>
__global__ __launch_bounds__(256) void kW_split(const float* __restrict__ W)
{
    uint32_t* dst = (WS == 1) ? g_W1s : g_W2s;
    const int OC  = (WS == 1) ? C1 : C2;
    int idx = blockIdx.x * 256 + threadIdx.x;
    int o   = idx >> 7;
    int kp  = idx & 127;
    if (o >= OC) return;
    float2 v = *(const float2*)(W + (size_t)o * C1 + 2 * kp);
    uint16_t h0, l0, h1, l1;
    bsplit(v.x, h0, l0); bsplit(v.y, h1, l1);
    dst[(size_t)o * 128 + kp]                    = pk(h0, h1);
    dst[(size_t)OC * 128 + (size_t)o * 128 + kp] = pk(l0, l1);
}

// ============================================================
// K1: edge aggregation, pipelined.
//   E: register prefetch + in-register masked row-sum (deterministic)
//   B (g_Pt): cp.async double-buffered
//   dyn smem: shA[2][128][20] (20480B) + shB[2buf][2][128][20] (40960B)
// ============================================================
__global__ __launch_bounds__(256) void k1_mma(
    const float* __restrict__ E0, const float* __restrict__ E1)
{
    extern __shared__ uint32_t dyn[];
    uint32_t (*shA)[128][20]    = (uint32_t(*)[128][20])dyn;
    uint32_t (*shB)[2][128][20] = (uint32_t(*)[2][128][20])(dyn + 2 * 128 * 20);
    __shared__ float sRow[128];
    __shared__ float sInv[128];

    const int tid  = threadIdx.x;
    const int lane = tid & 31;
    const int wid  = tid >> 5;
    const int wr   = wid & 1;
    const int wc   = wid >> 1;
    const int b    = blockIdx.y;
    const int ez   = blockIdx.z;
    const int row0 = blockIdx.x * 128;
    const float* __restrict__ E = (ez ? E1 : E0) + (size_t)b * NN * NN;
    const uint32_t* __restrict__ Pt = g_Pt + (size_t)b * 2 * DD * (NN / 2);
    const uint32_t bB = smem_u32(shB);

    float acc[4][4][4];
#pragma unroll
    for (int i = 0; i < 4; i++)
#pragma unroll
        for (int j = 0; j < 4; j++)
#pragma unroll
            for (int k = 0; k < 4; k++) acc[i][j][k] = 0.f;

    const int q4 = (tid & 7) * 4;          // k-quad offset for this thread
    int rl[4];
#pragma unroll
    for (int l = 0; l < 4; l++) rl[l] = l * 32 + (tid >> 3);
    float rs[4] = {0.f, 0.f, 0.f, 0.f};

    // prologue: E regs for it=0, cp.async B it=0 -> buf0
    float4 ev[4];
#pragma unroll
    for (int l = 0; l < 4; l++)
        ev[l] = *(const float4*)(E + (size_t)(row0 + rl[l]) * NN + q4);
#pragma unroll
    for (int l = 0; l < 4; l++) {
        int idx = l * 256 + tid;
        int pb = idx >> 9, rem = idx & 511, n = rem >> 2, c4 = (rem & 3) * 4;
        cpasync16(bB + (((pb * 128) + n) * 20 + c4) * 4,
                  Pt + ((size_t)pb * DD + n) * (NN / 2) + c4);
    }
    CP_COMMIT();

    for (int it = 0; it < 16; it++) {
        const int k0  = it * 32;
        const int cur = it & 1;
        CP_WAIT0();
        __syncthreads();                      // prev compute done + B[cur] visible

        // convert E regs -> shA; accumulate raw masked row-sum
#pragma unroll
        for (int l = 0; l < 4; l++) {
            int grow = row0 + rl[l];
            int gk   = k0 + q4;
            float4 v = ev[l];
            if (grow == gk)     v.x = 0.f;
            if (grow == gk + 1) v.y = 0.f;
            if (grow == gk + 2) v.z = 0.f;
            if (grow == gk + 3) v.w = 0.f;
            rs[l] += (v.x + v.y) + (v.z + v.w);
            uint16_t h0, l0, h1, l1, h2, l2, h3, l3;
            bsplit(v.x, h0, l0); bsplit(v.y, h1, l1);
            bsplit(v.z, h2, l2); bsplit(v.w, h3, l3);
            int kp = (tid & 7) * 2;
            shA[0][rl[l]][kp]     = pk(h0, h1);
            shA[0][rl[l]][kp + 1] = pk(h2, h3);
            shA[1][rl[l]][kp]     = pk(l0, l1);
            shA[1][rl[l]][kp + 1] = pk(l2, l3);
        }
        if (it < 15) {
#pragma unroll
            for (int l = 0; l < 4; l++)
                ev[l] = *(const float4*)(E + (size_t)(row0 + rl[l]) * NN + k0 + 32 + q4);
        }
        __syncthreads();                      // shA ready

        if (it < 15) {
            const int kh = (k0 + 32) >> 1;
#pragma unroll
            for (int l = 0; l < 4; l++) {
                int idx = l * 256 + tid;
                int pb = idx >> 9, rem = idx & 511, n = rem >> 2, c4 = (rem & 3) * 4;
                cpasync16(bB + ((((1 - cur) * 2 + pb) * 128 + n) * 20 + c4) * 4,
                          Pt + ((size_t)pb * DD + n) * (NN / 2) + kh + c4);
            }
            CP_COMMIT();
        }
        compute_chunk(shA, shB[cur], acc, wr, wc, lane);
    }

    // row-sum reduce (8-lane groups, deterministic tree)
#pragma unroll
    for (int l = 0; l < 4; l++) {
        float v = rs[l];
        v += __shfl_down_sync(0xffffffffu, v, 4);
        v += __shfl_down_sync(0xffffffffu, v, 2);
        v += __shfl_down_sync(0xffffffffu, v, 1);
        if ((tid & 7) == 0) sRow[rl[l]] = v;
    }
    __syncthreads();
    if (tid < 128) sInv[tid] = 1.0f / fmaxf(sRow[tid], 1e-12f);
    __syncthreads();

    // epilogue: scale, split, store g_Xs planes
#pragma unroll
    for (int mf = 0; mf < 4; mf++) {
        int rll = wr * 64 + mf * 16 + (lane >> 2);
#pragma unroll
        for (int nf = 0; nf < 4; nf++) {
            int kpo = ez * 64 + wc * 16 + nf * 4 + (lane & 3);
            float i0 = sInv[rll], i1 = sInv[rll + 8];
            size_t m0r = (size_t)b * NN + row0 + rll;
            size_t m1r = m0r + 8;
            uint16_t h0, l0, h1, l1;
            bsplit(acc[mf][nf][0] * i0, h0, l0);
            bsplit(acc[mf][nf][1] * i0, h1, l1);
            g_Xs[m0r * 128 + kpo]                      = pk(h0, h1);
            g_Xs[(size_t)MTOT * 128 + m0r * 128 + kpo] = pk(l0, l1);
            bsplit(acc[mf][nf][2] * i1, h0, l0);
            bsplit(acc[mf][nf][3] * i1, h1, l1);
            g_Xs[m1r * 128 + kpo]                      = pk(h0, h1);
            g_Xs[(size_t)MTOT * 128 + m1r * 128 + kpo] = pk(l0, l1);
        }
    }
}

// ============================================================
// GEMM1: fully cp.async double-buffered (A = g_Xs, B = g_W1s), 1 sync/iter
//   dyn smem: shA[2][2][128][20] + shB[2][2][128][20] = 81920B
// ============================================================
__global__ __launch_bounds__(256) void k_gemm1(void)
{
    extern __shared__ uint32_t dyn[];
    uint32_t (*shA)[2][128][20] = (uint32_t(*)[2][128][20])dyn;
    uint32_t (*shB)[2][128][20] = (uint32_t(*)[2][128][20])(dyn + 2 * 2 * 128 * 20);

    const int tid  = threadIdx.x;
    const int lane = tid & 31;
    const int wid  = tid >> 5;
    const int wr   = wid & 1;
    const int wc   = wid >> 1;
    const size_t m0 = (size_t)blockIdx.x * 128;
    const int    o0 = blockIdx.y * 128;
    const uint32_t bA = smem_u32(shA);
    const uint32_t bBs = smem_u32(shB);

    float acc[4][4][4];
#pragma unroll
    for (int i = 0; i < 4; i++)
#pragma unroll
        for (int j = 0; j < 4; j++)
#pragma unroll
            for (int k = 0; k < 4; k++) acc[i][j][k] = 0.f;

    // prologue: it=0 -> buf0
#pragma unroll
    for (int l = 0; l < 4; l++) {
        int idx = l * 256 + tid;
        int pa = idx >> 9, rem = idx & 511, r = rem >> 2, c4 = (rem & 3) * 4;
        cpasync16(bA + (((pa * 128) + r) * 20 + c4) * 4,
                  g_Xs + (size_t)pa * MTOT * 128 + (m0 + r) * 128 + c4);
        cpasync16(bBs + (((pa * 128) + r) * 20 + c4) * 4,
                  g_W1s + (size_t)pa * C1 * 128 + (size_t)(o0 + r) * 128 + c4);
    }
    CP_COMMIT();

    for (int it = 0; it < 8; it++) {
        const int cur = it & 1;
        CP_WAIT0();
        __syncthreads();
        if (it < 7) {
            const int kh = (it + 1) * 16;
#pragma unroll
            for (int l = 0; l < 4; l++) {
                int idx = l * 256 + tid;
                int pa = idx >> 9, rem = idx & 511, r = rem >> 2, c4 = (rem & 3) * 4;
                cpasync16(bA + ((((1 - cur) * 2 + pa) * 128 + r) * 20 + c4) * 4,
                          g_Xs + (size_t)pa * MTOT * 128 + (m0 + r) * 128 + kh + c4);
                cpasync16(bBs + ((((1 - cur) * 2 + pa) * 128 + r) * 20 + c4) * 4,
                          g_W1s + (size_t)pa * C1 * 128 + (size_t)(o0 + r) * 128 + kh + c4);
            }
            CP_COMMIT();
        }
        compute_chunk(shA[cur], shB[cur], acc, wr, wc, lane);
    }

#pragma unroll
    for (int mf = 0; mf < 4; mf++) {
        int rl = wr * 64 + mf * 16 + (lane >> 2);
#pragma unroll
        for (int nf = 0; nf < 4; nf++) {
            int col = o0 + wc * 32 + nf * 8 + (lane & 3) * 2;
            float* d0 = g_Y1 + (m0 + rl) * C1 + col;
            float* d1 = g_Y1 + (m0 + rl + 8) * C1 + col;
            *(float2*)d0 = { acc[mf][nf][0], acc[mf][nf][1] };
            *(float2*)d1 = { acc[mf][nf][2], acc[mf][nf][3] };
        }
    }
}

// ============================================================
// GEMM2: A = bn1+lrelu(g_Y1) reg-prefetch + split; B cp.async double-buffered
//   dyn smem: shA[2][128][20] + shB[2][2][128][20] = 61440B
// ============================================================
__global__ __launch_bounds__(256) void k_gemm2(float* __restrict__ out)
{
    extern __shared__ uint32_t dyn[];
    uint32_t (*shA)[128][20]    = (uint32_t(*)[128][20])dyn;
    uint32_t (*shB)[2][128][20] = (uint32_t(*)[2][128][20])(dyn + 2 * 128 * 20);
    __shared__ float sBNa[C1], sBNc[C1];

    const int tid  = threadIdx.x;
    const int lane = tid & 31;
    const int wid  = tid >> 5;
    const int wr   = wid & 1;
    const int wc   = wid >> 1;
    const size_t m0 = (size_t)blockIdx.x * 128;
    const uint32_t bBs = smem_u32(shB);

    sBNa[tid] = g_ab[tid];
    sBNc[tid] = g_ab[C1 + tid];

    float acc[4][4][4];
#pragma unroll
    for (int i = 0; i < 4; i++)
#pragma unroll
        for (int j = 0; j < 4; j++)
#pragma unroll
            for (int k = 0; k < 4; k++) acc[i][j][k] = 0.f;

    const int rA  = tid >> 1;             // A row this thread converts (2 rows/thread? no: 8 chunks)
    // per-thread A mapping: idx = l*256+tid -> r = idx>>4, kp = idx&15  (8 l's)
    float2 ev[8];
#pragma unroll
    for (int l = 0; l < 8; l++) {
        int idx = l * 256 + tid;
        int r = idx >> 4, kp = idx & 15;
        ev[l] = *(const float2*)(g_Y1 + (m0 + r) * C1 + 2 * kp);
    }
#pragma unroll
    for (int l = 0; l < 4; l++) {
        int idx = l * 256 + tid;
        int pb = idx >> 9, rem = idx & 511, n = rem >> 2, c4 = (rem & 3) * 4;
        cpasync16(bBs + (((pb * 128) + n) * 20 + c4) * 4,
                  g_W2s + (size_t)pb * C2 * 128 + (size_t)n * 128 + c4);
    }
    CP_COMMIT();
    (void)rA;

    for (int it = 0; it < 8; it++) {
        const int k0  = it * 32;
        const int cur = it & 1;
        CP_WAIT0();
        __syncthreads();

#pragma unroll
        for (int l = 0; l < 8; l++) {
            int idx = l * 256 + tid;
            int r = idx >> 4, kp = idx & 15;
            int ch = k0 + 2 * kp;
            float2 v = ev[l];
            v.x = lrelu(fmaf(sBNa[ch],     v.x, sBNc[ch]));
            v.y = lrelu(fmaf(sBNa[ch + 1], v.y, sBNc[ch + 1]));
            uint16_t h0, l0, h1, l1;
            bsplit(v.x, h0, l0); bsplit(v.y, h1, l1);
            shA[0][r][kp] = pk(h0, h1);
            shA[1][r][kp] = pk(l0, l1);
        }
        if (it < 7) {
#pragma unroll
            for (int l = 0; l < 8; l++) {
                int idx = l * 256 + tid;
                int r = idx >> 4, kp = idx & 15;
                ev[l] = *(const float2*)(g_Y1 + (m0 + r) * C1 + k0 + 32 + 2 * kp);
            }
        }
        __syncthreads();

        if (it < 7) {
            const int kh = (k0 + 32) >> 1;
#pragma unroll
            for (int l = 0; l < 4; l++) {
                int idx = l * 256 + tid;
                int pb = idx >> 9, rem = idx & 511, n = rem >> 2, c4 = (rem & 3) * 4;
                cpasync16(bBs + ((((1 - cur) * 2 + pb) * 128 + n) * 20 + c4) * 4,
                          g_W2s + (size_t)pb * C2 * 128 + (size_t)n * 128 + kh + c4);
            }
            CP_COMMIT();
        }
        compute_chunk(shA, shB[cur], acc, wr, wc, lane);
    }

#pragma unroll
    for (int mf = 0; mf < 4; mf++) {
        int rl = wr * 64 + mf * 16 + (lane >> 2);
#pragma unroll
        for (int nf = 0; nf < 4; nf++) {
            int col = wc * 32 + nf * 8 + (lane & 3) * 2;
            float* d0 = out + (m0 + rl) * C2 + col;
            float* d1 = out + (m0 + rl + 8) * C2 + col;
            *(float2*)d0 = { acc[mf][nf][0], acc[mf][nf][1] };
            *(float2*)d1 = { acc[mf][nf][2], acc[mf][nf][3] };
        }
    }
}

// ============================================================
// stats + finalize + final BN
// ============================================================
template <int STAGE, int C>
__global__ void k_stats(const float* __restrict__ ext, int rpb)
{
    const float* __restrict__ Y = (STAGE == 1) ? g_Y1 : ext;
    const int c  = threadIdx.x;
    const size_t r0 = (size_t)blockIdx.x * rpb;
    double s[8] = {0, 0, 0, 0, 0, 0, 0, 0};
    double q[8] = {0, 0, 0, 0, 0, 0, 0, 0};
    for (int r = 0; r < rpb; r += 8) {
#pragma unroll
        for (int j = 0; j < 8; j++) {
            double v = (double)Y[(r0 + r + j) * C + c];
            s[j] += v;
            q[j] += v * v;
        }
    }
    double ss = ((s[0] + s[1]) + (s[2] + s[3])) + ((s[4] + s[5]) + (s[6] + s[7]));
    double qq = ((q[0] + q[1]) + (q[2] + q[3])) + ((q[4] + q[5]) + (q[6] + q[7]));
    g_partd[blockIdx.x * (2 * C) + c]     = ss;
    g_partd[blockIdx.x * (2 * C) + C + c] = qq;
}

template <int C, int NBLK>
__global__ __launch_bounds__(256) void k_finalize(
    const float* __restrict__ g, const float* __restrict__ bb, int aoff)
{
    __shared__ double ss[256], sq[256];
    const int c   = blockIdx.x;
    const int tid = threadIdx.x;
    double s = 0.0, q = 0.0;
    for (int i = tid; i < NBLK; i += 256) {
        s += g_partd[(size_t)i * (2 * C) + c];
        q += g_partd[(size_t)i * (2 * C) + C + c];
    }
    ss[tid] = s; sq[tid] = q;
    __syncthreads();
    for (int off = 128; off > 0; off >>= 1) {
        if (tid < off) { ss[tid] += ss[tid + off]; sq[tid] += sq[tid + off]; }
        __syncthreads();
    }
    if (tid == 0) {
        const double invM = 1.0 / (double)MTOT;
        double mean = ss[0] * invM;
        double var  = sq[0] * invM - mean * mean;
        float a = (float)((double)g[c] / sqrt(var + 1e-5));
        g_ab[aoff + c]     = a;
        g_ab[aoff + C + c] = (float)((double)bb[c] - mean * (double)a);
    }
}

__global__ __launch_bounds__(256) void k_bn_act2(float* __restrict__ Y)
{
    size_t i4 = (size_t)blockIdx.x * blockDim.x + threadIdx.x;
    int c4 = (int)(i4 & (C2 / 4 - 1)) * 4;
    float4 v  = ((float4*)Y)[i4];
    float4 av = *(const float4*)&g_ab[2 * C1 + c4];
    float4 cv = *(const float4*)&g_ab[2 * C1 + C2 + c4];
    v.x = lrelu(fmaf(av.x, v.x, cv.x));
    v.y = lrelu(fmaf(av.y, v.y, cv.y));
    v.z = lrelu(fmaf(av.z, v.z, cv.z));
    v.w = lrelu(fmaf(av.w, v.w, cv.w));
    ((float4*)Y)[i4] = v;
}

// ============================================================
extern "C" void kernel_launch(void* const* d_in, const int* in_sizes, int n_in,
                              void* d_out, int out_size)
{
    (void)in_sizes; (void)n_in; (void)out_size;
    const float* E0 = (const float*)d_in[0];
    const float* E1 = (const float*)d_in[1];
    const float* P  = (const float*)d_in[2];
    const float* W1 = (const float*)d_in[3];
    const float* g1 = (const float*)d_in[4];
    const float* b1 = (const float*)d_in[5];
    const float* W2 = (const float*)d_in[6];
    const float* g2 = (const float*)d_in[7];
    const float* b2 = (const float*)d_in[8];
    float* out = (float*)d_out;

    cudaFuncSetAttribute(k1_mma,  cudaFuncAttributeMaxDynamicSharedMemorySize, 61440);
    cudaFuncSetAttribute(k_gemm1, cudaFuncAttributeMaxDynamicSharedMemorySize, 81920);
    cudaFuncSetAttribute(k_gemm2, cudaFuncAttributeMaxDynamicSharedMemorySize, 61440);

    // 0. one-time conversions
    kP_split<<<dim3(MB, 8), 256>>>(P);
    kW_split<1><<<(C1 * 128) / 256, 256>>>(W1);
    kW_split<2><<<(C2 * 128) / 256, 256>>>(W2);

    // 1. edge aggregation (pipelined) -> g_Xs
    k1_mma<<<dim3(4, MB, 2), 256, 61440>>>(E0, E1);

    // 2. GEMM1 (pipelined, pure-copy tiles)
    k_gemm1<<<dim3(MTOT / 128, 2), 256, 81920>>>();

    // 3. BN1 stats + parallel finalize (BN1+LReLU fused into GEMM2)
    k_stats<1, C1><<<512, C1>>>(nullptr, MTOT / 512);
    k_finalize<C1, 512><<<C1, 256>>>(g1, b1, 0);

    // 4. GEMM2 (pipelined)
    k_gemm2<<<dim3(MTOT / 128, 1), 256, 61440>>>(out);

    // 5. BN2 stats + finalize + in-place BN2+LReLU
    k_stats<2, C2><<<512, C2>>>(out, MTOT / 512);
    k_finalize<C2, 512><<<C2, 256>>>(g2, b2, 2 * C1);
    k_bn_act2<<<16384, 256>>>(out);
}

// round 10
// speedup vs baseline: 2.5649x; 1.0921x over previous
#include <cuda_runtime.h>
#include <cuda_bf16.h>
#include <cstdint>

// Problem constants
#define MB   256
#define NN   512
#define DD   128
#define C1   256
#define C2   128
#define MTOT (MB * NN)

// ---------------- scratch ----------------
__device__ uint32_t g_Pt[(size_t)MB * 2 * DD * (NN / 2)];
__device__ uint32_t g_Xs[2 * (size_t)MTOT * (C1 / 2)];
__device__ float    g_Y1[(size_t)MTOT * C1];
__device__ uint32_t g_W1s[2 * C1 * (C1 / 2)];
__device__ uint32_t g_W2s[2 * C2 * (C1 / 2)];
__device__ double   g_partd[512 * 2 * C1];
__device__ float    g_ab[2 * C1 + 2 * C2];

__device__ __forceinline__ float lrelu(float y) { return y >= 0.f ? y : 0.01f * y; }

// ---------------- helpers ----------------
__device__ __forceinline__ void bsplit(float x, uint16_t& h, uint16_t& l) {
    __nv_bfloat16 hb = __float2bfloat16(x);
    float r = x - __bfloat162float(hb);
    __nv_bfloat16 lb = __float2bfloat16(r);
    h = __bfloat16_as_ushort(hb);
    l = __bfloat16_as_ushort(lb);
}
__device__ __forceinline__ uint32_t pk(uint16_t a, uint16_t b) {
    return (uint32_t)a | ((uint32_t)b << 16);
}
__device__ __forceinline__ uint32_t smem_u32(const void* p) {
    uint32_t a;
    asm("{ .reg .u64 t; cvta.to.shared.u64 t, %1; cvt.u32.u64 %0, t; }" : "=r"(a) : "l"(p));
    return a;
}
__device__ __forceinline__ void cpasync16(uint32_t saddr, const void* g) {
    asm volatile("cp.async.cg.shared.global [%0], [%1], 16;" :: "r"(saddr), "l"(g));
}
#define CP_COMMIT() asm volatile("cp.async.commit_group;" ::: "memory")
#define CP_WAIT0()  asm volatile("cp.async.wait_group 0;" ::: "memory")

__device__ __forceinline__ void mma16816(float* c, const uint32_t* a, const uint32_t* b) {
    asm volatile(
        "mma.sync.aligned.m16n8k16.row.col.f32.bf16.bf16.f32 "
        "{%0,%1,%2,%3}, {%4,%5,%6,%7}, {%8,%9}, {%0,%1,%2,%3};"
        : "+f"(c[0]), "+f"(c[1]), "+f"(c[2]), "+f"(c[3])
        : "r"(a[0]), "r"(a[1]), "r"(a[2]), "r"(a[3]), "r"(b[0]), "r"(b[1]));
}
__device__ __forceinline__ void ldsm4(uint32_t& r0, uint32_t& r1, uint32_t& r2,
                                      uint32_t& r3, uint32_t a) {
    asm volatile("ldmatrix.sync.aligned.m8n8.x4.shared.b16 {%0,%1,%2,%3}, [%4];"
        : "=r"(r0), "=r"(r1), "=r"(r2), "=r"(r3) : "r"(a));
}

// ---------------- warp-tile compute over one 32-k chunk (ldmatrix) ----------
// aB/bB: u32 smem byte-addresses of [2][128][20] u32 arrays (plane = 10240B).
// 3 passes hh + hl + lh; A frags loaded once per (plane, ks), reused.
#define PLANE 10240u
__device__ __forceinline__ void compute_chunk(
    uint32_t aB, uint32_t bB, float acc[4][4][4], int wr, int wc, int lane)
{
    const int l7  = lane & 7;
    const int tb0 = (lane >> 3) & 1;
    const int tb1 = (lane >> 4) & 1;
#pragma unroll
    for (int ks = 0; ks < 2; ks++) {
        uint32_t ah[4][4], al[4][4], bh[2][4], bl[2][4];
#pragma unroll
        for (int mf = 0; mf < 4; mf++) {
            uint32_t off = ((uint32_t)(wr * 64 + mf * 16 + tb0 * 8 + l7) * 20
                            + (uint32_t)(ks * 8 + tb1 * 4)) * 4;
            ldsm4(ah[mf][0], ah[mf][1], ah[mf][2], ah[mf][3], aB + off);
            ldsm4(al[mf][0], al[mf][1], al[mf][2], al[mf][3], aB + PLANE + off);
        }
#pragma unroll
        for (int np = 0; np < 2; np++) {
            uint32_t off = ((uint32_t)(wc * 32 + np * 16 + tb1 * 8 + l7) * 20
                            + (uint32_t)(ks * 8 + tb0 * 4)) * 4;
            ldsm4(bh[np][0], bh[np][1], bh[np][2], bh[np][3], bB + off);
            ldsm4(bl[np][0], bl[np][1], bl[np][2], bl[np][3], bB + PLANE + off);
        }
#pragma unroll
        for (int mf = 0; mf < 4; mf++)
#pragma unroll
            for (int nf = 0; nf < 4; nf++)
                mma16816(acc[mf][nf], ah[mf], &bh[nf >> 1][(nf & 1) * 2]);
#pragma unroll
        for (int mf = 0; mf < 4; mf++)
#pragma unroll
            for (int nf = 0; nf < 4; nf++)
                mma16816(acc[mf][nf], ah[mf], &bl[nf >> 1][(nf & 1) * 2]);
#pragma unroll
        for (int mf = 0; mf < 4; mf++)
#pragma unroll
            for (int nf = 0; nf < 4; nf++)
                mma16816(acc[mf][nf], al[mf], &bh[nf >> 1][(nf & 1) * 2]);
    }
}

// ============================================================
// kP: P -> transposed split planes g_Pt[b][pa][d][kp]
// ============================================================
__global__ __launch_bounds__(256) void kP_split(const float* __restrict__ P)
{
    __shared__ uint16_t sH16[128][66];
    __shared__ uint16_t sL16[128][66];

    const int tid = threadIdx.x;
    const int b   = blockIdx.x;
    const int kt  = blockIdx.y;
    const float* __restrict__ Pb = P + ((size_t)b * NN + kt * 64) * DD;

#pragma unroll
    for (int l = 0; l < 16; l++) {
        int idx = l * 256 + tid;
        int k   = idx >> 6;
        int d2  = idx & 63;
        float2 v = *(const float2*)(Pb + (size_t)k * DD + 2 * d2);
        uint16_t h0, l0, h1, l1;
        bsplit(v.x, h0, l0); bsplit(v.y, h1, l1);
        sH16[2 * d2][k]     = h0; sL16[2 * d2][k]     = l0;
        sH16[2 * d2 + 1][k] = h1; sL16[2 * d2 + 1][k] = l1;
    }
    __syncthreads();
#pragma unroll
    for (int l = 0; l < 32; l++) {
        int idx = l * 256 + tid;
        int pa  = idx >> 12;
        int rem = idx & 4095;
        int d   = rem >> 5;
        int kp  = rem & 31;
        const uint16_t* s = pa ? &sL16[d][0] : &sH16[d][0];
        g_Pt[(((size_t)b * 2 + pa) * DD + d) * (NN / 2) + kt * 32 + kp] =
            pk(s[2 * kp], s[2 * kp + 1]);
    }
}

// ============================================================
// kW: weight split
// ============================================================
template <int WS>
__global__ __launch_bounds__(256) void kW_split(const float* __restrict__ W)
{
    uint32_t* dst = (WS == 1) ? g_W1s : g_W2s;
    const int OC  = (WS == 1) ? C1 : C2;
    int idx = blockIdx.x * 256 + threadIdx.x;
    int o   = idx >> 7;
    int kp  = idx & 127;
    if (o >= OC) return;
    float2 v = *(const float2*)(W + (size_t)o * C1 + 2 * kp);
    uint16_t h0, l0, h1, l1;
    bsplit(v.x, h0, l0); bsplit(v.y, h1, l1);
    dst[(size_t)o * 128 + kp]                    = pk(h0, h1);
    dst[(size_t)OC * 128 + (size_t)o * 128 + kp] = pk(l0, l1);
}

// ============================================================
// K1: edge aggregation, pipelined (E reg-prefetch, B cp.async dbl-buffered)
// ============================================================
__global__ __launch_bounds__(256) void k1_mma(
    const float* __restrict__ E0, const float* __restrict__ E1)
{
    extern __shared__ uint32_t dyn[];
    uint32_t (*shA)[128][20] = (uint32_t(*)[128][20])dyn;
    __shared__ float sRow[128];
    __shared__ float sInv[128];

    const int tid  = threadIdx.x;
    const int lane = tid & 31;
    const int wid  = tid >> 5;
    const int wr   = wid & 1;
    const int wc   = wid >> 1;
    const int b    = blockIdx.y;
    const int ez   = blockIdx.z;
    const int row0 = blockIdx.x * 128;
    const float* __restrict__ E = (ez ? E1 : E0) + (size_t)b * NN * NN;
    const uint32_t* __restrict__ Pt = g_Pt + (size_t)b * 2 * DD * (NN / 2);
    const uint32_t aA = smem_u32(dyn);
    const uint32_t bB = aA + 2 * PLANE;           // shB base (2 bufs x 2 planes)

    float acc[4][4][4];
#pragma unroll
    for (int i = 0; i < 4; i++)
#pragma unroll
        for (int j = 0; j < 4; j++)
#pragma unroll
            for (int k = 0; k < 4; k++) acc[i][j][k] = 0.f;

    const int q4 = (tid & 7) * 4;
    int rl[4];
#pragma unroll
    for (int l = 0; l < 4; l++) rl[l] = l * 32 + (tid >> 3);
    float rs[4] = {0.f, 0.f, 0.f, 0.f};

    float4 ev[4];
#pragma unroll
    for (int l = 0; l < 4; l++)
        ev[l] = *(const float4*)(E + (size_t)(row0 + rl[l]) * NN + q4);
#pragma unroll
    for (int l = 0; l < 4; l++) {
        int idx = l * 256 + tid;
        int pb = idx >> 9, rem = idx & 511, n = rem >> 2, c4 = (rem & 3) * 4;
        cpasync16(bB + ((pb * 128 + n) * 20 + c4) * 4,
                  Pt + ((size_t)pb * DD + n) * (NN / 2) + c4);
    }
    CP_COMMIT();

    for (int it = 0; it < 16; it++) {
        const int k0  = it * 32;
        const int cur = it & 1;
        CP_WAIT0();
        __syncthreads();

#pragma unroll
        for (int l = 0; l < 4; l++) {
            int grow = row0 + rl[l];
            int gk   = k0 + q4;
            float4 v = ev[l];
            if (grow == gk)     v.x = 0.f;
            if (grow == gk + 1) v.y = 0.f;
            if (grow == gk + 2) v.z = 0.f;
            if (grow == gk + 3) v.w = 0.f;
            rs[l] += (v.x + v.y) + (v.z + v.w);
            uint16_t h0, l0, h1, l1, h2, l2, h3, l3;
            bsplit(v.x, h0, l0); bsplit(v.y, h1, l1);
            bsplit(v.z, h2, l2); bsplit(v.w, h3, l3);
            int kp = (tid & 7) * 2;
            shA[0][rl[l]][kp]     = pk(h0, h1);
            shA[0][rl[l]][kp + 1] = pk(h2, h3);
            shA[1][rl[l]][kp]     = pk(l0, l1);
            shA[1][rl[l]][kp + 1] = pk(l2, l3);
        }
        if (it < 15) {
#pragma unroll
            for (int l = 0; l < 4; l++)
                ev[l] = *(const float4*)(E + (size_t)(row0 + rl[l]) * NN + k0 + 32 + q4);
        }
        __syncthreads();

        if (it < 15) {
            const int kh = (k0 + 32) >> 1;
#pragma unroll
            for (int l = 0; l < 4; l++) {
                int idx = l * 256 + tid;
                int pb = idx >> 9, rem = idx & 511, n = rem >> 2, c4 = (rem & 3) * 4;
                cpasync16(bB + (1 - cur) * 2 * PLANE + ((pb * 128 + n) * 20 + c4) * 4,
                          Pt + ((size_t)pb * DD + n) * (NN / 2) + kh + c4);
            }
            CP_COMMIT();
        }
        compute_chunk(aA, bB + cur * 2 * PLANE, acc, wr, wc, lane);
    }

#pragma unroll
    for (int l = 0; l < 4; l++) {
        float v = rs[l];
        v += __shfl_down_sync(0xffffffffu, v, 4);
        v += __shfl_down_sync(0xffffffffu, v, 2);
        v += __shfl_down_sync(0xffffffffu, v, 1);
        if ((tid & 7) == 0) sRow[rl[l]] = v;
    }
    __syncthreads();
    if (tid < 128) sInv[tid] = 1.0f / fmaxf(sRow[tid], 1e-12f);
    __syncthreads();

#pragma unroll
    for (int mf = 0; mf < 4; mf++) {
        int rll = wr * 64 + mf * 16 + (lane >> 2);
#pragma unroll
        for (int nf = 0; nf < 4; nf++) {
            int kpo = ez * 64 + wc * 16 + nf * 4 + (lane & 3);
            float i0 = sInv[rll], i1 = sInv[rll + 8];
            size_t m0r = (size_t)b * NN + row0 + rll;
            size_t m1r = m0r + 8;
            uint16_t h0, l0, h1, l1;
            bsplit(acc[mf][nf][0] * i0, h0, l0);
            bsplit(acc[mf][nf][1] * i0, h1, l1);
            g_Xs[m0r * 128 + kpo]                      = pk(h0, h1);
            g_Xs[(size_t)MTOT * 128 + m0r * 128 + kpo] = pk(l0, l1);
            bsplit(acc[mf][nf][2] * i1, h0, l0);
            bsplit(acc[mf][nf][3] * i1, h1, l1);
            g_Xs[m1r * 128 + kpo]                      = pk(h0, h1);
            g_Xs[(size_t)MTOT * 128 + m1r * 128 + kpo] = pk(l0, l1);
        }
    }
}

// ============================================================
// GEMM1: fully cp.async double-buffered, 1 sync/iter
// ============================================================
__global__ __launch_bounds__(256) void k_gemm1(void)
{
    extern __shared__ uint32_t dyn[];

    const int tid  = threadIdx.x;
    const int lane = tid & 31;
    const int wid  = tid >> 5;
    const int wr   = wid & 1;
    const int wc   = wid >> 1;
    const size_t m0 = (size_t)blockIdx.x * 128;
    const int    o0 = blockIdx.y * 128;
    const uint32_t bA  = smem_u32(dyn);            // shA: 2 bufs x 2 planes
    const uint32_t bBs = bA + 4 * PLANE;           // shB: 2 bufs x 2 planes

    float acc[4][4][4];
#pragma unroll
    for (int i = 0; i < 4; i++)
#pragma unroll
        for (int j = 0; j < 4; j++)
#pragma unroll
            for (int k = 0; k < 4; k++) acc[i][j][k] = 0.f;

#pragma unroll
    for (int l = 0; l < 4; l++) {
        int idx = l * 256 + tid;
        int pa = idx >> 9, rem = idx & 511, r = rem >> 2, c4 = (rem & 3) * 4;
        cpasync16(bA + ((pa * 128 + r) * 20 + c4) * 4,
                  g_Xs + (size_t)pa * MTOT * 128 + (m0 + r) * 128 + c4);
        cpasync16(bBs + ((pa * 128 + r) * 20 + c4) * 4,
                  g_W1s + (size_t)pa * C1 * 128 + (size_t)(o0 + r) * 128 + c4);
    }
    CP_COMMIT();

    for (int it = 0; it < 8; it++) {
        const int cur = it & 1;
        CP_WAIT0();
        __syncthreads();
        if (it < 7) {
            const int kh = (it + 1) * 16;
#pragma unroll
            for (int l = 0; l < 4; l++) {
                int idx = l * 256 + tid;
                int pa = idx >> 9, rem = idx & 511, r = rem >> 2, c4 = (rem & 3) * 4;
                cpasync16(bA + (1 - cur) * 2 * PLANE + ((pa * 128 + r) * 20 + c4) * 4,
                          g_Xs + (size_t)pa * MTOT * 128 + (m0 + r) * 128 + kh + c4);
                cpasync16(bBs + (1 - cur) * 2 * PLANE + ((pa * 128 + r) * 20 + c4) * 4,
                          g_W1s + (size_t)pa * C1 * 128 + (size_t)(o0 + r) * 128 + kh + c4);
            }
            CP_COMMIT();
        }
        compute_chunk(bA + cur * 2 * PLANE, bBs + cur * 2 * PLANE, acc, wr, wc, lane);
    }

#pragma unroll
    for (int mf = 0; mf < 4; mf++) {
        int rl = wr * 64 + mf * 16 + (lane >> 2);
#pragma unroll
        for (int nf = 0; nf < 4; nf++) {
            int col = o0 + wc * 32 + nf * 8 + (lane & 3) * 2;
            float* d0 = g_Y1 + (m0 + rl) * C1 + col;
            float* d1 = g_Y1 + (m0 + rl + 8) * C1 + col;
            *(float2*)d0 = { acc[mf][nf][0], acc[mf][nf][1] };
            *(float2*)d1 = { acc[mf][nf][2], acc[mf][nf][3] };
        }
    }
}

// ============================================================
// GEMM2: A = bn1+lrelu(g_Y1) reg-prefetch; B cp.async double-buffered
// ============================================================
__global__ __launch_bounds__(256) void k_gemm2(float* __restrict__ out)
{
    extern __shared__ uint32_t dyn[];
    uint32_t (*shA)[128][20] = (uint32_t(*)[128][20])dyn;
    __shared__ float sBNa[C1], sBNc[C1];

    const int tid  = threadIdx.x;
    const int lane = tid & 31;
    const int wid  = tid >> 5;
    const int wr   = wid & 1;
    const int wc   = wid >> 1;
    const size_t m0 = (size_t)blockIdx.x * 128;
    const uint32_t aA  = smem_u32(dyn);
    const uint32_t bBs = aA + 2 * PLANE;

    sBNa[tid] = g_ab[tid];
    sBNc[tid] = g_ab[C1 + tid];

    float acc[4][4][4];
#pragma unroll
    for (int i = 0; i < 4; i++)
#pragma unroll
        for (int j = 0; j < 4; j++)
#pragma unroll
            for (int k = 0; k < 4; k++) acc[i][j][k] = 0.f;

    float2 ev[8];
#pragma unroll
    for (int l = 0; l < 8; l++) {
        int idx = l * 256 + tid;
        int r = idx >> 4, kp = idx & 15;
        ev[l] = *(const float2*)(g_Y1 + (m0 + r) * C1 + 2 * kp);
    }
#pragma unroll
    for (int l = 0; l < 4; l++) {
        int idx = l * 256 + tid;
        int pb = idx >> 9, rem = idx & 511, n = rem >> 2, c4 = (rem & 3) * 4;
        cpasync16(bBs + ((pb * 128 + n) * 20 + c4) * 4,
                  g_W2s + (size_t)pb * C2 * 128 + (size_t)n * 128 + c4);
    }
    CP_COMMIT();

    for (int it = 0; it < 8; it++) {
        const int k0  = it * 32;
        const int cur = it & 1;
        CP_WAIT0();
        __syncthreads();

#pragma unroll
        for (int l = 0; l < 8; l++) {
            int idx = l * 256 + tid;
            int r = idx >> 4, kp = idx & 15;
            int ch = k0 + 2 * kp;
            float2 v = ev[l];
            v.x = lrelu(fmaf(sBNa[ch],     v.x, sBNc[ch]));
            v.y = lrelu(fmaf(sBNa[ch + 1], v.y, sBNc[ch + 1]));
            uint16_t h0, l0, h1, l1;
            bsplit(v.x, h0, l0); bsplit(v.y, h1, l1);
            shA[0][r][kp] = pk(h0, h1);
            shA[1][r][kp] = pk(l0, l1);
        }
        if (it < 7) {
#pragma unroll
            for (int l = 0; l < 8; l++) {
                int idx = l * 256 + tid;
                int r = idx >> 4, kp = idx & 15;
                ev[l] = *(const float2*)(g_Y1 + (m0 + r) * C1 + k0 + 32 + 2 * kp);
            }
        }
        __syncthreads();

        if (it < 7) {
            const int kh = (k0 + 32) >> 1;
#pragma unroll
            for (int l = 0; l < 4; l++) {
                int idx = l * 256 + tid;
                int pb = idx >> 9, rem = idx & 511, n = rem >> 2, c4 = (rem & 3) * 4;
                cpasync16(bBs + (1 - cur) * 2 * PLANE + ((pb * 128 + n) * 20 + c4) * 4,
                          g_W2s + (size_t)pb * C2 * 128 + (size_t)n * 128 + kh + c4);
            }
            CP_COMMIT();
        }
        compute_chunk(aA, bBs + cur * 2 * PLANE, acc, wr, wc, lane);
    }

#pragma unroll
    for (int mf = 0; mf < 4; mf++) {
        int rl = wr * 64 + mf * 16 + (lane >> 2);
#pragma unroll
        for (int nf = 0; nf < 4; nf++) {
            int col = wc * 32 + nf * 8 + (lane & 3) * 2;
            float* d0 = out + (m0 + rl) * C2 + col;
            float* d1 = out + (m0 + rl + 8) * C2 + col;
            *(float2*)d0 = { acc[mf][nf][0], acc[mf][nf][1] };
            *(float2*)d1 = { acc[mf][nf][2], acc[mf][nf][3] };
        }
    }
}

// ============================================================
// stats + finalize + final BN
// ============================================================
template <int STAGE, int C>
__global__ void k_stats(const float* __restrict__ ext, int rpb)
{
    const float* __restrict__ Y = (STAGE == 1) ? g_Y1 : ext;
    const int c  = threadIdx.x;
    const size_t r0 = (size_t)blockIdx.x * rpb;
    double s[8] = {0, 0, 0, 0, 0, 0, 0, 0};
    double q[8] = {0, 0, 0, 0, 0, 0, 0, 0};
    for (int r = 0; r < rpb; r += 8) {
#pragma unroll
        for (int j = 0; j < 8; j++) {
            double v = (double)Y[(r0 + r + j) * C + c];
            s[j] += v;
            q[j] += v * v;
        }
    }
    double ss = ((s[0] + s[1]) + (s[2] + s[3])) + ((s[4] + s[5]) + (s[6] + s[7]));
    double qq = ((q[0] + q[1]) + (q[2] + q[3])) + ((q[4] + q[5]) + (q[6] + q[7]));
    g_partd[blockIdx.x * (2 * C) + c]     = ss;
    g_partd[blockIdx.x * (2 * C) + C + c] = qq;
}

template <int C, int NBLK>
__global__ __launch_bounds__(256) void k_finalize(
    const float* __restrict__ g, const float* __restrict__ bb, int aoff)
{
    __shared__ double ss[256], sq[256];
    const int c   = blockIdx.x;
    const int tid = threadIdx.x;
    double s = 0.0, q = 0.0;
    for (int i = tid; i < NBLK; i += 256) {
        s += g_partd[(size_t)i * (2 * C) + c];
        q += g_partd[(size_t)i * (2 * C) + C + c];
    }
    ss[tid] = s; sq[tid] = q;
    __syncthreads();
    for (int off = 128; off > 0; off >>= 1) {
        if (tid < off) { ss[tid] += ss[tid + off]; sq[tid] += sq[tid + off]; }
        __syncthreads();
    }
    if (tid == 0) {
        const double invM = 1.0 / (double)MTOT;
        double mean = ss[0] * invM;
        double var  = sq[0] * invM - mean * mean;
        float a = (float)((double)g[c] / sqrt(var + 1e-5));
        g_ab[aoff + c]     = a;
        g_ab[aoff + C + c] = (float)((double)bb[c] - mean * (double)a);
    }
}

__global__ __launch_bounds__(256) void k_bn_act2(float* __restrict__ Y)
{
    size_t i4 = (size_t)blockIdx.x * blockDim.x + threadIdx.x;
    int c4 = (int)(i4 & (C2 / 4 - 1)) * 4;
    float4 v  = ((float4*)Y)[i4];
    float4 av = *(const float4*)&g_ab[2 * C1 + c4];
    float4 cv = *(const float4*)&g_ab[2 * C1 + C2 + c4];
    v.x = lrelu(fmaf(av.x, v.x, cv.x));
    v.y = lrelu(fmaf(av.y, v.y, cv.y));
    v.z = lrelu(fmaf(av.z, v.z, cv.z));
    v.w = lrelu(fmaf(av.w, v.w, cv.w));
    ((float4*)Y)[i4] = v;
}

// ============================================================
extern "C" void kernel_launch(void* const* d_in, const int* in_sizes, int n_in,
                              void* d_out, int out_size)
{
    (void)in_sizes; (void)n_in; (void)out_size;
    const float* E0 = (const float*)d_in[0];
    const float* E1 = (const float*)d_in[1];
    const float* P  = (const float*)d_in[2];
    const float* W1 = (const float*)d_in[3];
    const float* g1 = (const float*)d_in[4];
    const float* b1 = (const float*)d_in[5];
    const float* W2 = (const float*)d_in[6];
    const float* g2 = (const float*)d_in[7];
    const float* b2 = (const float*)d_in[8];
    float* out = (float*)d_out;

    cudaFuncSetAttribute(k1_mma,  cudaFuncAttributeMaxDynamicSharedMemorySize, 61440);
    cudaFuncSetAttribute(k_gemm1, cudaFuncAttributeMaxDynamicSharedMemorySize, 81920);
    cudaFuncSetAttribute(k_gemm2, cudaFuncAttributeMaxDynamicSharedMemorySize, 61440);

    // 0. one-time conversions
    kP_split<<<dim3(MB, 8), 256>>>(P);
    kW_split<1><<<(C1 * 128) / 256, 256>>>(W1);
    kW_split<2><<<(C2 * 128) / 256, 256>>>(W2);

    // 1. edge aggregation (pipelined, ldmatrix) -> g_Xs
    k1_mma<<<dim3(4, MB, 2), 256, 61440>>>(E0, E1);

    // 2. GEMM1 (pipelined, ldmatrix)
    k_gemm1<<<dim3(MTOT / 128, 2), 256, 81920>>>();

    // 3. BN1 stats + parallel finalize (BN1+LReLU fused into GEMM2)
    k_stats<1, C1><<<512, C1>>>(nullptr, MTOT / 512);
    k_finalize<C1, 512><<<C1, 256>>>(g1, b1, 0);

    // 4. GEMM2 (pipelined, ldmatrix)
    k_gemm2<<<dim3(MTOT / 128, 1), 256, 61440>>>(out);

    // 5. BN2 stats + finalize + in-place BN2+LReLU
    k_stats<2, C2><<<512, C2>>>(out, MTOT / 512);
    k_finalize<C2, 512><<<C2, 256>>>(g2, b2, 2 * C1);
    k_bn_act2<<<16384, 256>>>(out);
}

// round 11
// speedup vs baseline: 3.5499x; 1.3841x over previous
#include <cuda_runtime.h>
#include <cuda_bf16.h>
#include <cstdint>

// Problem constants
#define MB   256
#define NN   512
#define DD   128
#define C1   256
#define C2   128
#define MTOT (MB * NN)

// ---------------- scratch ----------------
__device__ uint32_t g_Pt[(size_t)MB * 2 * DD * (NN / 2)];
__device__ uint32_t g_Xs[2 * (size_t)MTOT * (C1 / 2)];
__device__ float    g_Y1[(size_t)MTOT * C1];
__device__ uint32_t g_W1s[2 * C1 * (C1 / 2)];
__device__ uint32_t g_W2s[2 * C2 * (C1 / 2)];
__device__ float    g_partS[256 * 1024];
__device__ float    g_partQ[256 * 1024];
__device__ float    g_ab[2 * C1 + 2 * C2];

__device__ __forceinline__ float lrelu(float y) { return y >= 0.f ? y : 0.01f * y; }

// ---------------- helpers ----------------
__device__ __forceinline__ void bsplit(float x, uint16_t& h, uint16_t& l) {
    __nv_bfloat16 hb = __float2bfloat16(x);
    float r = x - __bfloat162float(hb);
    __nv_bfloat16 lb = __float2bfloat16(r);
    h = __bfloat16_as_ushort(hb);
    l = __bfloat16_as_ushort(lb);
}
__device__ __forceinline__ uint32_t pk(uint16_t a, uint16_t b) {
    return (uint32_t)a | ((uint32_t)b << 16);
}
__device__ __forceinline__ uint32_t smem_u32(const void* p) {
    uint32_t a;
    asm("{ .reg .u64 t; cvta.to.shared.u64 t, %1; cvt.u32.u64 %0, t; }" : "=r"(a) : "l"(p));
    return a;
}
__device__ __forceinline__ void cpasync16(uint32_t saddr, const void* g) {
    asm volatile("cp.async.cg.shared.global [%0], [%1], 16;" :: "r"(saddr), "l"(g));
}
#define CP_COMMIT() asm volatile("cp.async.commit_group;" ::: "memory")
#define CP_WAIT0()  asm volatile("cp.async.wait_group 0;" ::: "memory")

__device__ __forceinline__ void mma16816(float* c, const uint32_t* a, const uint32_t* b) {
    asm volatile(
        "mma.sync.aligned.m16n8k16.row.col.f32.bf16.bf16.f32 "
        "{%0,%1,%2,%3}, {%4,%5,%6,%7}, {%8,%9}, {%0,%1,%2,%3};"
        : "+f"(c[0]), "+f"(c[1]), "+f"(c[2]), "+f"(c[3])
        : "r"(a[0]), "r"(a[1]), "r"(a[2]), "r"(a[3]), "r"(b[0]), "r"(b[1]));
}
__device__ __forceinline__ void ldsm4(uint32_t& r0, uint32_t& r1, uint32_t& r2,
                                      uint32_t& r3, uint32_t a) {
    asm volatile("ldmatrix.sync.aligned.m8n8.x4.shared.b16 {%0,%1,%2,%3}, [%4];"
        : "=r"(r0), "=r"(r1), "=r"(r2), "=r"(r3) : "r"(a));
}

// ---------------- warp-tile compute over one 32-k chunk (ldmatrix) ----------
#define PLANE  10240u           // bytes per [128][20] u32 plane
#define PLANEW 2560             // u32 words per plane
__device__ __forceinline__ void compute_chunk(
    uint32_t aB, uint32_t bB, float acc[4][4][4], int wr, int wc, int lane)
{
    const int l7  = lane & 7;
    const int tb0 = (lane >> 3) & 1;
    const int tb1 = (lane >> 4) & 1;
#pragma unroll
    for (int ks = 0; ks < 2; ks++) {
        uint32_t ah[4][4], al[4][4], bh[2][4], bl[2][4];
#pragma unroll
        for (int mf = 0; mf < 4; mf++) {
            uint32_t off = ((uint32_t)(wr * 64 + mf * 16 + tb0 * 8 + l7) * 20
                            + (uint32_t)(ks * 8 + tb1 * 4)) * 4;
            ldsm4(ah[mf][0], ah[mf][1], ah[mf][2], ah[mf][3], aB + off);
            ldsm4(al[mf][0], al[mf][1], al[mf][2], al[mf][3], aB + PLANE + off);
        }
#pragma unroll
        for (int np = 0; np < 2; np++) {
            uint32_t off = ((uint32_t)(wc * 32 + np * 16 + tb1 * 8 + l7) * 20
                            + (uint32_t)(ks * 8 + tb0 * 4)) * 4;
            ldsm4(bh[np][0], bh[np][1], bh[np][2], bh[np][3], bB + off);
            ldsm4(bl[np][0], bl[np][1], bl[np][2], bl[np][3], bB + PLANE + off);
        }
#pragma unroll
        for (int mf = 0; mf < 4; mf++)
#pragma unroll
            for (int nf = 0; nf < 4; nf++)
                mma16816(acc[mf][nf], ah[mf], &bh[nf >> 1][(nf & 1) * 2]);
#pragma unroll
        for (int mf = 0; mf < 4; mf++)
#pragma unroll
            for (int nf = 0; nf < 4; nf++)
                mma16816(acc[mf][nf], ah[mf], &bl[nf >> 1][(nf & 1) * 2]);
#pragma unroll
        for (int mf = 0; mf < 4; mf++)
#pragma unroll
            for (int nf = 0; nf < 4; nf++)
                mma16816(acc[mf][nf], al[mf], &bh[nf >> 1][(nf & 1) * 2]);
    }
}

// ---------------- fused per-CTA BN stats epilogue (deterministic) ----------
// sPS/sPQ: [128][17] floats.  chBase = first channel of this CTA, bx = CTA idx.
__device__ __forceinline__ void stats_epilogue(
    const float acc[4][4][4], int wr, int wc, int lane, int tid,
    float* sPS, float* sPQ, int chBase, int bx)
{
    const int ci = wr * 8 + (lane >> 2);
#pragma unroll
    for (int nf = 0; nf < 4; nf++)
#pragma unroll
        for (int c01 = 0; c01 < 2; c01++) {
            int col = wc * 32 + nf * 8 + (lane & 3) * 2 + c01;
            float s = 0.f, q = 0.f;
#pragma unroll
            for (int mf = 0; mf < 4; mf++) {
                float y0 = acc[mf][nf][c01];
                float y1 = acc[mf][nf][2 + c01];
                s += y0 + y1;
                q += y0 * y0 + y1 * y1;
            }
            sPS[col * 17 + ci] = s;
            sPQ[col * 17 + ci] = q;
        }
    __syncthreads();
    if (tid < 128) {
        float s = 0.f, q = 0.f;
#pragma unroll
        for (int i = 0; i < 16; i++) {
            s += sPS[tid * 17 + i];
            q += sPQ[tid * 17 + i];
        }
        g_partS[(size_t)(chBase + tid) * 1024 + bx] = s;
        g_partQ[(size_t)(chBase + tid) * 1024 + bx] = q;
    }
}

// ============================================================
// kP: P -> transposed split planes g_Pt[b][pa][d][kp]
// ============================================================
__global__ __launch_bounds__(256) void kP_split(const float* __restrict__ P)
{
    __shared__ uint16_t sH16[128][66];
    __shared__ uint16_t sL16[128][66];

    const int tid = threadIdx.x;
    const int b   = blockIdx.x;
    const int kt  = blockIdx.y;
    const float* __restrict__ Pb = P + ((size_t)b * NN + kt * 64) * DD;

#pragma unroll
    for (int l = 0; l < 16; l++) {
        int idx = l * 256 + tid;
        int k   = idx >> 6;
        int d2  = idx & 63;
        float2 v = *(const float2*)(Pb + (size_t)k * DD + 2 * d2);
        uint16_t h0, l0, h1, l1;
        bsplit(v.x, h0, l0); bsplit(v.y, h1, l1);
        sH16[2 * d2][k]     = h0; sL16[2 * d2][k]     = l0;
        sH16[2 * d2 + 1][k] = h1; sL16[2 * d2 + 1][k] = l1;
    }
    __syncthreads();
#pragma unroll
    for (int l = 0; l < 32; l++) {
        int idx = l * 256 + tid;
        int pa  = idx >> 12;
        int rem = idx & 4095;
        int d   = rem >> 5;
        int kp  = rem & 31;
        const uint16_t* s = pa ? &sL16[d][0] : &sH16[d][0];
        g_Pt[(((size_t)b * 2 + pa) * DD + d) * (NN / 2) + kt * 32 + kp] =
            pk(s[2 * kp], s[2 * kp + 1]);
    }
}

// ============================================================
// kW: weight split
// ============================================================
template <int WS>
__global__ __launch_bounds__(256) void kW_split(const float* __restrict__ W)
{
    uint32_t* dst = (WS == 1) ? g_W1s : g_W2s;
    const int OC  = (WS == 1) ? C1 : C2;
    int idx = blockIdx.x * 256 + threadIdx.x;
    int o   = idx >> 7;
    int kp  = idx & 127;
    if (o >= OC) return;
    float2 v = *(const float2*)(W + (size_t)o * C1 + 2 * kp);
    uint16_t h0, l0, h1, l1;
    bsplit(v.x, h0, l0); bsplit(v.y, h1, l1);
    dst[(size_t)o * 128 + kp]                    = pk(h0, h1);
    dst[(size_t)OC * 128 + (size_t)o * 128 + kp] = pk(l0, l1);
}

// ============================================================
// K1: edge aggregation.  shA AND shB double-buffered: 1 barrier/iter;
//   E conversion overlaps next-B cp.async wait.  dyn smem 81920B.
// ============================================================
__device__ __forceinline__ void k1_convert(
    const float4 ev[4], int k0, int row0, const int rl[4], int q4, int kp,
    uint32_t (*pA)[128][20], float rs[4])
{
#pragma unroll
    for (int l = 0; l < 4; l++) {
        int grow = row0 + rl[l];
        int gk   = k0 + q4;
        float4 v = ev[l];
        if (grow == gk)     v.x = 0.f;
        if (grow == gk + 1) v.y = 0.f;
        if (grow == gk + 2) v.z = 0.f;
        if (grow == gk + 3) v.w = 0.f;
        rs[l] += (v.x + v.y) + (v.z + v.w);
        uint16_t h0, l0, h1, l1, h2, l2, h3, l3;
        bsplit(v.x, h0, l0); bsplit(v.y, h1, l1);
        bsplit(v.z, h2, l2); bsplit(v.w, h3, l3);
        pA[0][rl[l]][kp]     = pk(h0, h1);
        pA[0][rl[l]][kp + 1] = pk(h2, h3);
        pA[1][rl[l]][kp]     = pk(l0, l1);
        pA[1][rl[l]][kp + 1] = pk(l2, l3);
    }
}

__global__ __launch_bounds__(256) void k1_mma(
    const float* __restrict__ E0, const float* __restrict__ E1)
{
    extern __shared__ uint32_t dyn[];
    __shared__ float sRow[128];
    __shared__ float sInv[128];

    const int tid  = threadIdx.x;
    const int lane = tid & 31;
    const int wid  = tid >> 5;
    const int wr   = wid & 1;
    const int wc   = wid >> 1;
    const int b    = blockIdx.y;
    const int ez   = blockIdx.z;
    const int row0 = blockIdx.x * 128;
    const float* __restrict__ E = (ez ? E1 : E0) + (size_t)b * NN * NN;
    const uint32_t* __restrict__ Pt = g_Pt + (size_t)b * 2 * DD * (NN / 2);
    const uint32_t aA = smem_u32(dyn);            // shA: 2 bufs x 2 planes
    const uint32_t bB = aA + 4 * PLANE;           // shB: 2 bufs x 2 planes

    float acc[4][4][4];
#pragma unroll
    for (int i = 0; i < 4; i++)
#pragma unroll
        for (int j = 0; j < 4; j++)
#pragma unroll
            for (int k = 0; k < 4; k++) acc[i][j][k] = 0.f;

    const int q4 = (tid & 7) * 4;
    const int kp = (tid & 7) * 2;
    int rl[4];
#pragma unroll
    for (int l = 0; l < 4; l++) rl[l] = l * 32 + (tid >> 3);
    float rs[4] = {0.f, 0.f, 0.f, 0.f};
    float4 ev[4];

    // ---- prologue: convert it0 into bufA0; preload E(it1); cp.async B(it0) ----
#pragma unroll
    for (int l = 0; l < 4; l++)
        ev[l] = *(const float4*)(E + (size_t)(row0 + rl[l]) * NN + q4);
    k1_convert(ev, 0, row0, rl, q4, kp, (uint32_t(*)[128][20])dyn, rs);
#pragma unroll
    for (int l = 0; l < 4; l++)
        ev[l] = *(const float4*)(E + (size_t)(row0 + rl[l]) * NN + 32 + q4);
#pragma unroll
    for (int l = 0; l < 4; l++) {
        int idx = l * 256 + tid;
        int pb = idx >> 9, rem = idx & 511, n = rem >> 2, c4 = (rem & 3) * 4;
        cpasync16(bB + ((pb * 128 + n) * 20 + c4) * 4,
                  Pt + ((size_t)pb * DD + n) * (NN / 2) + c4);
    }
    CP_COMMIT();
    CP_WAIT0();
    __syncthreads();

    for (int it = 0; it < 16; it++) {
        const int cur = it & 1;
        const int nxt = cur ^ 1;
        if (it < 15) {
            const int kh = (it + 1) * 16;
#pragma unroll
            for (int l = 0; l < 4; l++) {
                int idx = l * 256 + tid;
                int pb = idx >> 9, rem = idx & 511, n = rem >> 2, c4 = (rem & 3) * 4;
                cpasync16(bB + nxt * 2 * PLANE + ((pb * 128 + n) * 20 + c4) * 4,
                          Pt + ((size_t)pb * DD + n) * (NN / 2) + kh + c4);
            }
            CP_COMMIT();
        }
        compute_chunk(aA + cur * 2 * PLANE, bB + cur * 2 * PLANE, acc, wr, wc, lane);
        if (it < 15)
            k1_convert(ev, (it + 1) * 32, row0, rl, q4, kp,
                       ((uint32_t(*)[128][20])dyn) + nxt * 2, rs);
        if (it < 14) {
#pragma unroll
            for (int l = 0; l < 4; l++)
                ev[l] = *(const float4*)(E + (size_t)(row0 + rl[l]) * NN
                                         + (it + 2) * 32 + q4);
        }
        if (it < 15) { CP_WAIT0(); __syncthreads(); }
    }

    // row-sum reduce (8-lane groups, deterministic tree)
#pragma unroll
    for (int l = 0; l < 4; l++) {
        float v = rs[l];
        v += __shfl_down_sync(0xffffffffu, v, 4);
        v += __shfl_down_sync(0xffffffffu, v, 2);
        v += __shfl_down_sync(0xffffffffu, v, 1);
        if ((tid & 7) == 0) sRow[rl[l]] = v;
    }
    __syncthreads();
    if (tid < 128) sInv[tid] = 1.0f / fmaxf(sRow[tid], 1e-12f);
    __syncthreads();

    // epilogue: scale, split, store g_Xs planes
#pragma unroll
    for (int mf = 0; mf < 4; mf++) {
        int rll = wr * 64 + mf * 16 + (lane >> 2);
#pragma unroll
        for (int nf = 0; nf < 4; nf++) {
            int kpo = ez * 64 + wc * 16 + nf * 4 + (lane & 3);
            float i0 = sInv[rll], i1 = sInv[rll + 8];
            size_t m0r = (size_t)b * NN + row0 + rll;
            size_t m1r = m0r + 8;
            uint16_t h0, l0, h1, l1;
            bsplit(acc[mf][nf][0] * i0, h0, l0);
            bsplit(acc[mf][nf][1] * i0, h1, l1);
            g_Xs[m0r * 128 + kpo]                      = pk(h0, h1);
            g_Xs[(size_t)MTOT * 128 + m0r * 128 + kpo] = pk(l0, l1);
            bsplit(acc[mf][nf][2] * i1, h0, l0);
            bsplit(acc[mf][nf][3] * i1, h1, l1);
            g_Xs[m1r * 128 + kpo]                      = pk(h0, h1);
            g_Xs[(size_t)MTOT * 128 + m1r * 128 + kpo] = pk(l0, l1);
        }
    }
}

// ============================================================
// GEMM1: fully cp.async double-buffered + fused BN1 stats epilogue
// ============================================================
__global__ __launch_bounds__(256) void k_gemm1(void)
{
    extern __shared__ uint32_t dyn[];
    __shared__ float sPS[128 * 17], sPQ[128 * 17];

    const int tid  = threadIdx.x;
    const int lane = tid & 31;
    const int wid  = tid >> 5;
    const int wr   = wid & 1;
    const int wc   = wid >> 1;
    const size_t m0 = (size_t)blockIdx.x * 128;
    const int    o0 = blockIdx.y * 128;
    const uint32_t bA  = smem_u32(dyn);
    const uint32_t bBs = bA + 4 * PLANE;

    float acc[4][4][4];
#pragma unroll
    for (int i = 0; i < 4; i++)
#pragma unroll
        for (int j = 0; j < 4; j++)
#pragma unroll
            for (int k = 0; k < 4; k++) acc[i][j][k] = 0.f;

#pragma unroll
    for (int l = 0; l < 4; l++) {
        int idx = l * 256 + tid;
        int pa = idx >> 9, rem = idx & 511, r = rem >> 2, c4 = (rem & 3) * 4;
        cpasync16(bA + ((pa * 128 + r) * 20 + c4) * 4,
                  g_Xs + (size_t)pa * MTOT * 128 + (m0 + r) * 128 + c4);
        cpasync16(bBs + ((pa * 128 + r) * 20 + c4) * 4,
                  g_W1s + (size_t)pa * C1 * 128 + (size_t)(o0 + r) * 128 + c4);
    }
    CP_COMMIT();

    for (int it = 0; it < 8; it++) {
        const int cur = it & 1;
        CP_WAIT0();
        __syncthreads();
        if (it < 7) {
            const int kh = (it + 1) * 16;
#pragma unroll
            for (int l = 0; l < 4; l++) {
                int idx = l * 256 + tid;
                int pa = idx >> 9, rem = idx & 511, r = rem >> 2, c4 = (rem & 3) * 4;
                cpasync16(bA + (1 - cur) * 2 * PLANE + ((pa * 128 + r) * 20 + c4) * 4,
                          g_Xs + (size_t)pa * MTOT * 128 + (m0 + r) * 128 + kh + c4);
                cpasync16(bBs + (1 - cur) * 2 * PLANE + ((pa * 128 + r) * 20 + c4) * 4,
                          g_W1s + (size_t)pa * C1 * 128 + (size_t)(o0 + r) * 128 + kh + c4);
            }
            CP_COMMIT();
        }
        compute_chunk(bA + cur * 2 * PLANE, bBs + cur * 2 * PLANE, acc, wr, wc, lane);
    }

#pragma unroll
    for (int mf = 0; mf < 4; mf++) {
        int rl = wr * 64 + mf * 16 + (lane >> 2);
#pragma unroll
        for (int nf = 0; nf < 4; nf++) {
            int col = o0 + wc * 32 + nf * 8 + (lane & 3) * 2;
            float* d0 = g_Y1 + (m0 + rl) * C1 + col;
            float* d1 = g_Y1 + (m0 + rl + 8) * C1 + col;
            *(float2*)d0 = { acc[mf][nf][0], acc[mf][nf][1] };
            *(float2*)d1 = { acc[mf][nf][2], acc[mf][nf][3] };
        }
    }
    __syncthreads();   // ensure last compute done before sPS reuse barrier inside
    stats_epilogue(acc, wr, wc, lane, tid, sPS, sPQ, o0, blockIdx.x);
}

// ============================================================
// GEMM2: A = bn1+lrelu(g_Y1), conversion pipelined into shA[nxt];
//   1 barrier/iter; fused BN2 stats epilogue
// ============================================================
__global__ __launch_bounds__(256) void k_gemm2(float* __restrict__ out)
{
    extern __shared__ uint32_t dyn[];
    __shared__ float sBNa[C1], sBNc[C1];
    __shared__ float sPS[128 * 17], sPQ[128 * 17];

    const int tid  = threadIdx.x;
    const int lane = tid & 31;
    const int wid  = tid >> 5;
    const int wr   = wid & 1;
    const int wc   = wid >> 1;
    const size_t m0 = (size_t)blockIdx.x * 128;
    const uint32_t aA  = smem_u32(dyn);           // shA: 2 bufs x 2 planes
    const uint32_t bBs = aA + 4 * PLANE;          // shB: 2 bufs x 2 planes

    sBNa[tid] = g_ab[tid];
    sBNc[tid] = g_ab[C1 + tid];
    __syncthreads();

    float acc[4][4][4];
#pragma unroll
    for (int i = 0; i < 4; i++)
#pragma unroll
        for (int j = 0; j < 4; j++)
#pragma unroll
            for (int k = 0; k < 4; k++) acc[i][j][k] = 0.f;

    float2 ev[8];
    // ---- prologue: convert it0 into bufA0; preload A(it1); cp.async B(it0) ----
#pragma unroll
    for (int l = 0; l < 8; l++) {
        int idx = l * 256 + tid;
        int r = idx >> 4, kp2 = idx & 15;
        ev[l] = *(const float2*)(g_Y1 + (m0 + r) * C1 + 2 * kp2);
    }
    {
        uint32_t (*pA)[128][20] = (uint32_t(*)[128][20])dyn;
#pragma unroll
        for (int l = 0; l < 8; l++) {
            int idx = l * 256 + tid;
            int r = idx >> 4, kp2 = idx & 15;
            int ch = 2 * kp2;
            float2 v = ev[l];
            v.x = lrelu(fmaf(sBNa[ch],     v.x, sBNc[ch]));
            v.y = lrelu(fmaf(sBNa[ch + 1], v.y, sBNc[ch + 1]));
            uint16_t h0, l0, h1, l1;
            bsplit(v.x, h0, l0); bsplit(v.y, h1, l1);
            pA[0][r][kp2] = pk(h0, h1);
            pA[1][r][kp2] = pk(l0, l1);
        }
    }
#pragma unroll
    for (int l = 0; l < 8; l++) {
        int idx = l * 256 + tid;
        int r = idx >> 4, kp2 = idx & 15;
        ev[l] = *(const float2*)(g_Y1 + (m0 + r) * C1 + 32 + 2 * kp2);
    }
#pragma unroll
    for (int l = 0; l < 4; l++) {
        int idx = l * 256 + tid;
        int pb = idx >> 9, rem = idx & 511, n = rem >> 2, c4 = (rem & 3) * 4;
        cpasync16(bBs + ((pb * 128 + n) * 20 + c4) * 4,
                  g_W2s + (size_t)pb * C2 * 128 + (size_t)n * 128 + c4);
    }
    CP_COMMIT();
    CP_WAIT0();
    __syncthreads();

    for (int it = 0; it < 8; it++) {
        const int cur = it & 1;
        const int nxt = cur ^ 1;
        if (it < 7) {
            const int kh = (it + 1) * 16;
#pragma unroll
            for (int l = 0; l < 4; l++) {
                int idx = l * 256 + tid;
                int pb = idx >> 9, rem = idx & 511, n = rem >> 2, c4 = (rem & 3) * 4;
                cpasync16(bBs + nxt * 2 * PLANE + ((pb * 128 + n) * 20 + c4) * 4,
                          g_W2s + (size_t)pb * C2 * 128 + (size_t)n * 128 + kh + c4);
            }
            CP_COMMIT();
        }
        compute_chunk(aA + cur * 2 * PLANE, bBs + cur * 2 * PLANE, acc, wr, wc, lane);
        if (it < 7) {
            uint32_t (*pA)[128][20] = ((uint32_t(*)[128][20])dyn) + nxt * 2;
            const int k0 = (it + 1) * 32;
#pragma unroll
            for (int l = 0; l < 8; l++) {
                int idx = l * 256 + tid;
                int r = idx >> 4, kp2 = idx & 15;
                int ch = k0 + 2 * kp2;
                float2 v = ev[l];
                v.x = lrelu(fmaf(sBNa[ch],     v.x, sBNc[ch]));
                v.y = lrelu(fmaf(sBNa[ch + 1], v.y, sBNc[ch + 1]));
                uint16_t h0, l0, h1, l1;
                bsplit(v.x, h0, l0); bsplit(v.y, h1, l1);
                pA[0][r][kp2] = pk(h0, h1);
                pA[1][r][kp2] = pk(l0, l1);
            }
        }
        if (it < 6) {
#pragma unroll
            for (int l = 0; l < 8; l++) {
                int idx = l * 256 + tid;
                int r = idx >> 4, kp2 = idx & 15;
                ev[l] = *(const float2*)(g_Y1 + (m0 + r) * C1 + (it + 2) * 32 + 2 * kp2);
            }
        }
        if (it < 7) { CP_WAIT0(); __syncthreads(); }
    }

#pragma unroll
    for (int mf = 0; mf < 4; mf++) {
        int rl = wr * 64 + mf * 16 + (lane >> 2);
#pragma unroll
        for (int nf = 0; nf < 4; nf++) {
            int col = wc * 32 + nf * 8 + (lane & 3) * 2;
            float* d0 = out + (m0 + rl) * C2 + col;
            float* d1 = out + (m0 + rl + 8) * C2 + col;
            *(float2*)d0 = { acc[mf][nf][0], acc[mf][nf][1] };
            *(float2*)d1 = { acc[mf][nf][2], acc[mf][nf][3] };
        }
    }
    __syncthreads();
    stats_epilogue(acc, wr, wc, lane, tid, sPS, sPQ, 0, blockIdx.x);
}

// ============================================================
// finalize: one block per channel, reduce 1024 float partials in fp64
// ============================================================
template <int C>
__global__ __launch_bounds__(256) void k_finalizeF(
    const float* __restrict__ g, const float* __restrict__ bb, int aoff)
{
    __shared__ double ss[256], sq[256];
    const int c   = blockIdx.x;
    const int tid = threadIdx.x;
    double s = 0.0, q = 0.0;
    for (int i = tid; i < 1024; i += 256) {
        s += (double)g_partS[(size_t)c * 1024 + i];
        q += (double)g_partQ[(size_t)c * 1024 + i];
    }
    ss[tid] = s; sq[tid] = q;
    __syncthreads();
    for (int off = 128; off > 0; off >>= 1) {
        if (tid < off) { ss[tid] += ss[tid + off]; sq[tid] += sq[tid + off]; }
        __syncthreads();
    }
    if (tid == 0) {
        const double invM = 1.0 / (double)MTOT;
        double mean = ss[0] * invM;
        double var  = sq[0] * invM - mean * mean;
        float a = (float)((double)g[c] / sqrt(var + 1e-5));
        g_ab[aoff + c]     = a;
        g_ab[aoff + C + c] = (float)((double)bb[c] - mean * (double)a);
    }
}

__global__ __launch_bounds__(256) void k_bn_act2(float* __restrict__ Y)
{
    size_t i4 = (size_t)blockIdx.x * blockDim.x + threadIdx.x;
    int c4 = (int)(i4 & (C2 / 4 - 1)) * 4;
    float4 v  = ((float4*)Y)[i4];
    float4 av = *(const float4*)&g_ab[2 * C1 + c4];
    float4 cv = *(const float4*)&g_ab[2 * C1 + C2 + c4];
    v.x = lrelu(fmaf(av.x, v.x, cv.x));
    v.y = lrelu(fmaf(av.y, v.y, cv.y));
    v.z = lrelu(fmaf(av.z, v.z, cv.z));
    v.w = lrelu(fmaf(av.w, v.w, cv.w));
    ((float4*)Y)[i4] = v;
}

// ============================================================
extern "C" void kernel_launch(void* const* d_in, const int* in_sizes, int n_in,
                              void* d_out, int out_size)
{
    (void)in_sizes; (void)n_in; (void)out_size;
    const float* E0 = (const float*)d_in[0];
    const float* E1 = (const float*)d_in[1];
    const float* P  = (const float*)d_in[2];
    const float* W1 = (const float*)d_in[3];
    const float* g1 = (const float*)d_in[4];
    const float* b1 = (const float*)d_in[5];
    const float* W2 = (const float*)d_in[6];
    const float* g2 = (const float*)d_in[7];
    const float* b2 = (const float*)d_in[8];
    float* out = (float*)d_out;

    cudaFuncSetAttribute(k1_mma,  cudaFuncAttributeMaxDynamicSharedMemorySize, 81920);
    cudaFuncSetAttribute(k_gemm1, cudaFuncAttributeMaxDynamicSharedMemorySize, 81920);
    cudaFuncSetAttribute(k_gemm2, cudaFuncAttributeMaxDynamicSharedMemorySize, 81920);

    // 0. one-time conversions
    kP_split<<<dim3(MB, 8), 256>>>(P);
    kW_split<1><<<(C1 * 128) / 256, 256>>>(W1);
    kW_split<2><<<(C2 * 128) / 256, 256>>>(W2);

    // 1. edge aggregation (1 barrier/iter) -> g_Xs
    k1_mma<<<dim3(4, MB, 2), 256, 81920>>>(E0, E1);

    // 2. GEMM1 + fused BN1 stats
    k_gemm1<<<dim3(MTOT / 128, 2), 256, 81920>>>();
    k_finalizeF<C1><<<C1, 256>>>(g1, b1, 0);

    // 3. GEMM2 (BN1+LReLU on load) + fused BN2 stats
    k_gemm2<<<dim3(MTOT / 128, 1), 256, 81920>>>(out);
    k_finalizeF<C2><<<C2, 256>>>(g2, b2, 2 * C1);

    // 4. in-place BN2 + LReLU
    k_bn_act2<<<16384, 256>>>(out);
}

// round 12
// speedup vs baseline: 4.0236x; 1.1334x over previous
#include <cuda_runtime.h>
#include <cuda_bf16.h>
#include <cstdint>

// Problem constants
#define MB   256
#define NN   512
#define DD   128
#define C1   256
#define C2   128
#define MTOT (MB * NN)

// ---------------- scratch ----------------
__device__ uint32_t g_Pt[(size_t)MB * 2 * DD * (NN / 2)];
__device__ uint32_t g_Xs[2 * (size_t)MTOT * (C1 / 2)];
__device__ float    g_Y1[(size_t)MTOT * C1];
__device__ uint32_t g_W1s[2 * C1 * (C1 / 2)];
__device__ uint32_t g_W2s[2 * C2 * (C1 / 2)];
__device__ float    g_partS[256 * 1024];
__device__ float    g_partQ[256 * 1024];
__device__ float    g_ab[2 * C1 + 2 * C2];

__device__ __forceinline__ float lrelu(float y) { return y >= 0.f ? y : 0.01f * y; }

// ---------------- helpers ----------------
__device__ __forceinline__ void bsplit(float x, uint16_t& h, uint16_t& l) {
    __nv_bfloat16 hb = __float2bfloat16(x);
    float r = x - __bfloat162float(hb);
    __nv_bfloat16 lb = __float2bfloat16(r);
    h = __bfloat16_as_ushort(hb);
    l = __bfloat16_as_ushort(lb);
}
__device__ __forceinline__ uint32_t pk(uint16_t a, uint16_t b) {
    return (uint32_t)a | ((uint32_t)b << 16);
}
__device__ __forceinline__ uint32_t smem_u32(const void* p) {
    uint32_t a;
    asm("{ .reg .u64 t; cvta.to.shared.u64 t, %1; cvt.u32.u64 %0, t; }" : "=r"(a) : "l"(p));
    return a;
}
__device__ __forceinline__ void cpasync16(uint32_t saddr, const void* g) {
    asm volatile("cp.async.cg.shared.global [%0], [%1], 16;" :: "r"(saddr), "l"(g));
}
#define CP_COMMIT() asm volatile("cp.async.commit_group;" ::: "memory")
#define CP_WAIT0()  asm volatile("cp.async.wait_group 0;" ::: "memory")

__device__ __forceinline__ void mma16816(float* c, const uint32_t* a, const uint32_t* b) {
    asm volatile(
        "mma.sync.aligned.m16n8k16.row.col.f32.bf16.bf16.f32 "
        "{%0,%1,%2,%3}, {%4,%5,%6,%7}, {%8,%9}, {%0,%1,%2,%3};"
        : "+f"(c[0]), "+f"(c[1]), "+f"(c[2]), "+f"(c[3])
        : "r"(a[0]), "r"(a[1]), "r"(a[2]), "r"(a[3]), "r"(b[0]), "r"(b[1]));
}
__device__ __forceinline__ void ldsm4(uint32_t& r0, uint32_t& r1, uint32_t& r2,
                                      uint32_t& r3, uint32_t a) {
    asm volatile("ldmatrix.sync.aligned.m8n8.x4.shared.b16 {%0,%1,%2,%3}, [%4];"
        : "=r"(r0), "=r"(r1), "=r"(r2), "=r"(r3) : "r"(a));
}

// ---------------- warp-tile compute over one 32-k chunk (ldmatrix) ----------
#define PLANE 10240u            // bytes per [128][20] u32 plane
__device__ __forceinline__ void compute_chunk(
    uint32_t aB, uint32_t bB, float acc[4][4][4], int wr, int wc, int lane)
{
    const int l7  = lane & 7;
    const int tb0 = (lane >> 3) & 1;
    const int tb1 = (lane >> 4) & 1;
#pragma unroll
    for (int ks = 0; ks < 2; ks++) {
        uint32_t ah[4][4], al[4][4], bh[2][4], bl[2][4];
#pragma unroll
        for (int mf = 0; mf < 4; mf++) {
            uint32_t off = ((uint32_t)(wr * 64 + mf * 16 + tb0 * 8 + l7) * 20
                            + (uint32_t)(ks * 8 + tb1 * 4)) * 4;
            ldsm4(ah[mf][0], ah[mf][1], ah[mf][2], ah[mf][3], aB + off);
            ldsm4(al[mf][0], al[mf][1], al[mf][2], al[mf][3], aB + PLANE + off);
        }
#pragma unroll
        for (int np = 0; np < 2; np++) {
            uint32_t off = ((uint32_t)(wc * 32 + np * 16 + tb1 * 8 + l7) * 20
                            + (uint32_t)(ks * 8 + tb0 * 4)) * 4;
            ldsm4(bh[np][0], bh[np][1], bh[np][2], bh[np][3], bB + off);
            ldsm4(bl[np][0], bl[np][1], bl[np][2], bl[np][3], bB + PLANE + off);
        }
#pragma unroll
        for (int mf = 0; mf < 4; mf++)
#pragma unroll
            for (int nf = 0; nf < 4; nf++)
                mma16816(acc[mf][nf], ah[mf], &bh[nf >> 1][(nf & 1) * 2]);
#pragma unroll
        for (int mf = 0; mf < 4; mf++)
#pragma unroll
            for (int nf = 0; nf < 4; nf++)
                mma16816(acc[mf][nf], ah[mf], &bl[nf >> 1][(nf & 1) * 2]);
#pragma unroll
        for (int mf = 0; mf < 4; mf++)
#pragma unroll
            for (int nf = 0; nf < 4; nf++)
                mma16816(acc[mf][nf], al[mf], &bh[nf >> 1][(nf & 1) * 2]);
    }
}

// ---------------- fused per-CTA BN stats epilogue (deterministic) ----------
__device__ __forceinline__ void stats_epilogue(
    const float acc[4][4][4], int wr, int wc, int lane, int tid,
    float* sPS, float* sPQ, int chBase, int bx)
{
    const int ci = wr * 8 + (lane >> 2);
#pragma unroll
    for (int nf = 0; nf < 4; nf++)
#pragma unroll
        for (int c01 = 0; c01 < 2; c01++) {
            int col = wc * 32 + nf * 8 + (lane & 3) * 2 + c01;
            float s = 0.f, q = 0.f;
#pragma unroll
            for (int mf = 0; mf < 4; mf++) {
                float y0 = acc[mf][nf][c01];
                float y1 = acc[mf][nf][2 + c01];
                s += y0 + y1;
                q += y0 * y0 + y1 * y1;
            }
            sPS[col * 17 + ci] = s;
            sPQ[col * 17 + ci] = q;
        }
    __syncthreads();
    if (tid < 128) {
        float s = 0.f, q = 0.f;
#pragma unroll
        for (int i = 0; i < 16; i++) {
            s += sPS[tid * 17 + i];
            q += sPQ[tid * 17 + i];
        }
        g_partS[(size_t)(chBase + tid) * 1024 + bx] = s;
        g_partQ[(size_t)(chBase + tid) * 1024 + bx] = q;
    }
}

// ============================================================
// kP: P -> transposed split planes g_Pt[b][pa][d][kp]
// ============================================================
__global__ __launch_bounds__(256) void kP_split(const float* __restrict__ P)
{
    __shared__ uint16_t sH16[128][66];
    __shared__ uint16_t sL16[128][66];

    const int tid = threadIdx.x;
    const int b   = blockIdx.x;
    const int kt  = blockIdx.y;
    const float* __restrict__ Pb = P + ((size_t)b * NN + kt * 64) * DD;

#pragma unroll
    for (int l = 0; l < 16; l++) {
        int idx = l * 256 + tid;
        int k   = idx >> 6;
        int d2  = idx & 63;
        float2 v = *(const float2*)(Pb + (size_t)k * DD + 2 * d2);
        uint16_t h0, l0, h1, l1;
        bsplit(v.x, h0, l0); bsplit(v.y, h1, l1);
        sH16[2 * d2][k]     = h0; sL16[2 * d2][k]     = l0;
        sH16[2 * d2 + 1][k] = h1; sL16[2 * d2 + 1][k] = l1;
    }
    __syncthreads();
#pragma unroll
    for (int l = 0; l < 32; l++) {
        int idx = l * 256 + tid;
        int pa  = idx >> 12;
        int rem = idx & 4095;
        int d   = rem >> 5;
        int kp  = rem & 31;
        const uint16_t* s = pa ? &sL16[d][0] : &sH16[d][0];
        g_Pt[(((size_t)b * 2 + pa) * DD + d) * (NN / 2) + kt * 32 + kp] =
            pk(s[2 * kp], s[2 * kp + 1]);
    }
}

// ============================================================
// kW: weight split
// ============================================================
template <int WS>
__global__ __launch_bounds__(256) void kW_split(const float* __restrict__ W)
{
    uint32_t* dst = (WS == 1) ? g_W1s : g_W2s;
    const int OC  = (WS == 1) ? C1 : C2;
    int idx = blockIdx.x * 256 + threadIdx.x;
    int o   = idx >> 7;
    int kp  = idx & 127;
    if (o >= OC) return;
    float2 v = *(const float2*)(W + (size_t)o * C1 + 2 * kp);
    uint16_t h0, l0, h1, l1;
    bsplit(v.x, h0, l0); bsplit(v.y, h1, l1);
    dst[(size_t)o * 128 + kp]                    = pk(h0, h1);
    dst[(size_t)OC * 128 + (size_t)o * 128 + kp] = pk(l0, l1);
}

// ============================================================
// K1 (R10 structure): single-buffered shA (E reg-prefetch conversion),
//   double-buffered shB via cp.async, 2 barriers/iter, 61440B dyn smem,
//   128 regs -> 2 CTAs/SM.
// ============================================================
__global__ __launch_bounds__(256) void k1_mma(
    const float* __restrict__ E0, const float* __restrict__ E1)
{
    extern __shared__ uint32_t dyn[];
    uint32_t (*shA)[128][20] = (uint32_t(*)[128][20])dyn;
    __shared__ float sRow[128];
    __shared__ float sInv[128];

    const int tid  = threadIdx.x;
    const int lane = tid & 31;
    const int wid  = tid >> 5;
    const int wr   = wid & 1;
    const int wc   = wid >> 1;
    const int b    = blockIdx.y;
    const int ez   = blockIdx.z;
    const int row0 = blockIdx.x * 128;
    const float* __restrict__ E = (ez ? E1 : E0) + (size_t)b * NN * NN;
    const uint32_t* __restrict__ Pt = g_Pt + (size_t)b * 2 * DD * (NN / 2);
    const uint32_t aA = smem_u32(dyn);
    const uint32_t bB = aA + 2 * PLANE;           // shB base (2 bufs x 2 planes)

    float acc[4][4][4];
#pragma unroll
    for (int i = 0; i < 4; i++)
#pragma unroll
        for (int j = 0; j < 4; j++)
#pragma unroll
            for (int k = 0; k < 4; k++) acc[i][j][k] = 0.f;

    const int q4 = (tid & 7) * 4;
    int rl[4];
#pragma unroll
    for (int l = 0; l < 4; l++) rl[l] = l * 32 + (tid >> 3);
    float rs[4] = {0.f, 0.f, 0.f, 0.f};

    float4 ev[4];
#pragma unroll
    for (int l = 0; l < 4; l++)
        ev[l] = *(const float4*)(E + (size_t)(row0 + rl[l]) * NN + q4);
#pragma unroll
    for (int l = 0; l < 4; l++) {
        int idx = l * 256 + tid;
        int pb = idx >> 9, rem = idx & 511, n = rem >> 2, c4 = (rem & 3) * 4;
        cpasync16(bB + ((pb * 128 + n) * 20 + c4) * 4,
                  Pt + ((size_t)pb * DD + n) * (NN / 2) + c4);
    }
    CP_COMMIT();

    for (int it = 0; it < 16; it++) {
        const int k0  = it * 32;
        const int cur = it & 1;
        CP_WAIT0();
        __syncthreads();

#pragma unroll
        for (int l = 0; l < 4; l++) {
            int grow = row0 + rl[l];
            int gk   = k0 + q4;
            float4 v = ev[l];
            if (grow == gk)     v.x = 0.f;
            if (grow == gk + 1) v.y = 0.f;
            if (grow == gk + 2) v.z = 0.f;
            if (grow == gk + 3) v.w = 0.f;
            rs[l] += (v.x + v.y) + (v.z + v.w);
            uint16_t h0, l0, h1, l1, h2, l2, h3, l3;
            bsplit(v.x, h0, l0); bsplit(v.y, h1, l1);
            bsplit(v.z, h2, l2); bsplit(v.w, h3, l3);
            int kp = (tid & 7) * 2;
            shA[0][rl[l]][kp]     = pk(h0, h1);
            shA[0][rl[l]][kp + 1] = pk(h2, h3);
            shA[1][rl[l]][kp]     = pk(l0, l1);
            shA[1][rl[l]][kp + 1] = pk(l2, l3);
        }
        if (it < 15) {
#pragma unroll
            for (int l = 0; l < 4; l++)
                ev[l] = *(const float4*)(E + (size_t)(row0 + rl[l]) * NN + k0 + 32 + q4);
        }
        __syncthreads();

        if (it < 15) {
            const int kh = (k0 + 32) >> 1;
#pragma unroll
            for (int l = 0; l < 4; l++) {
                int idx = l * 256 + tid;
                int pb = idx >> 9, rem = idx & 511, n = rem >> 2, c4 = (rem & 3) * 4;
                cpasync16(bB + (1 - cur) * 2 * PLANE + ((pb * 128 + n) * 20 + c4) * 4,
                          Pt + ((size_t)pb * DD + n) * (NN / 2) + kh + c4);
            }
            CP_COMMIT();
        }
        compute_chunk(aA, bB + cur * 2 * PLANE, acc, wr, wc, lane);
    }

#pragma unroll
    for (int l = 0; l < 4; l++) {
        float v = rs[l];
        v += __shfl_down_sync(0xffffffffu, v, 4);
        v += __shfl_down_sync(0xffffffffu, v, 2);
        v += __shfl_down_sync(0xffffffffu, v, 1);
        if ((tid & 7) == 0) sRow[rl[l]] = v;
    }
    __syncthreads();
    if (tid < 128) sInv[tid] = 1.0f / fmaxf(sRow[tid], 1e-12f);
    __syncthreads();

#pragma unroll
    for (int mf = 0; mf < 4; mf++) {
        int rll = wr * 64 + mf * 16 + (lane >> 2);
#pragma unroll
        for (int nf = 0; nf < 4; nf++) {
            int kpo = ez * 64 + wc * 16 + nf * 4 + (lane & 3);
            float i0 = sInv[rll], i1 = sInv[rll + 8];
            size_t m0r = (size_t)b * NN + row0 + rll;
            size_t m1r = m0r + 8;
            uint16_t h0, l0, h1, l1;
            bsplit(acc[mf][nf][0] * i0, h0, l0);
            bsplit(acc[mf][nf][1] * i0, h1, l1);
            g_Xs[m0r * 128 + kpo]                      = pk(h0, h1);
            g_Xs[(size_t)MTOT * 128 + m0r * 128 + kpo] = pk(l0, l1);
            bsplit(acc[mf][nf][2] * i1, h0, l0);
            bsplit(acc[mf][nf][3] * i1, h1, l1);
            g_Xs[m1r * 128 + kpo]                      = pk(h0, h1);
            g_Xs[(size_t)MTOT * 128 + m1r * 128 + kpo] = pk(l0, l1);
        }
    }
}

// ============================================================
// GEMM1: fully cp.async double-buffered + fused BN1 stats epilogue
// ============================================================
__global__ __launch_bounds__(256) void k_gemm1(void)
{
    extern __shared__ uint32_t dyn[];
    __shared__ float sPS[128 * 17], sPQ[128 * 17];

    const int tid  = threadIdx.x;
    const int lane = tid & 31;
    const int wid  = tid >> 5;
    const int wr   = wid & 1;
    const int wc   = wid >> 1;
    const size_t m0 = (size_t)blockIdx.x * 128;
    const int    o0 = blockIdx.y * 128;
    const uint32_t bA  = smem_u32(dyn);
    const uint32_t bBs = bA + 4 * PLANE;

    float acc[4][4][4];
#pragma unroll
    for (int i = 0; i < 4; i++)
#pragma unroll
        for (int j = 0; j < 4; j++)
#pragma unroll
            for (int k = 0; k < 4; k++) acc[i][j][k] = 0.f;

#pragma unroll
    for (int l = 0; l < 4; l++) {
        int idx = l * 256 + tid;
        int pa = idx >> 9, rem = idx & 511, r = rem >> 2, c4 = (rem & 3) * 4;
        cpasync16(bA + ((pa * 128 + r) * 20 + c4) * 4,
                  g_Xs + (size_t)pa * MTOT * 128 + (m0 + r) * 128 + c4);
        cpasync16(bBs + ((pa * 128 + r) * 20 + c4) * 4,
                  g_W1s + (size_t)pa * C1 * 128 + (size_t)(o0 + r) * 128 + c4);
    }
    CP_COMMIT();

    for (int it = 0; it < 8; it++) {
        const int cur = it & 1;
        CP_WAIT0();
        __syncthreads();
        if (it < 7) {
            const int kh = (it + 1) * 16;
#pragma unroll
            for (int l = 0; l < 4; l++) {
                int idx = l * 256 + tid;
                int pa = idx >> 9, rem = idx & 511, r = rem >> 2, c4 = (rem & 3) * 4;
                cpasync16(bA + (1 - cur) * 2 * PLANE + ((pa * 128 + r) * 20 + c4) * 4,
                          g_Xs + (size_t)pa * MTOT * 128 + (m0 + r) * 128 + kh + c4);
                cpasync16(bBs + (1 - cur) * 2 * PLANE + ((pa * 128 + r) * 20 + c4) * 4,
                          g_W1s + (size_t)pa * C1 * 128 + (size_t)(o0 + r) * 128 + kh + c4);
            }
            CP_COMMIT();
        }
        compute_chunk(bA + cur * 2 * PLANE, bBs + cur * 2 * PLANE, acc, wr, wc, lane);
    }

#pragma unroll
    for (int mf = 0; mf < 4; mf++) {
        int rl = wr * 64 + mf * 16 + (lane >> 2);
#pragma unroll
        for (int nf = 0; nf < 4; nf++) {
            int col = o0 + wc * 32 + nf * 8 + (lane & 3) * 2;
            float* d0 = g_Y1 + (m0 + rl) * C1 + col;
            float* d1 = g_Y1 + (m0 + rl + 8) * C1 + col;
            *(float2*)d0 = { acc[mf][nf][0], acc[mf][nf][1] };
            *(float2*)d1 = { acc[mf][nf][2], acc[mf][nf][3] };
        }
    }
    __syncthreads();
    stats_epilogue(acc, wr, wc, lane, tid, sPS, sPQ, o0, blockIdx.x);
}

// ============================================================
// GEMM2: A = bn1+lrelu(g_Y1), conversion pipelined into shA[nxt];
//   1 barrier/iter; fused BN2 stats epilogue
// ============================================================
__global__ __launch_bounds__(256) void k_gemm2(float* __restrict__ out)
{
    extern __shared__ uint32_t dyn[];
    __shared__ float sBNa[C1], sBNc[C1];
    __shared__ float sPS[128 * 17], sPQ[128 * 17];

    const int tid  = threadIdx.x;
    const int lane = tid & 31;
    const int wid  = tid >> 5;
    const int wr   = wid & 1;
    const int wc   = wid >> 1;
    const size_t m0 = (size_t)blockIdx.x * 128;
    const uint32_t aA  = smem_u32(dyn);           // shA: 2 bufs x 2 planes
    const uint32_t bBs = aA + 4 * PLANE;          // shB: 2 bufs x 2 planes

    sBNa[tid] = g_ab[tid];
    sBNc[tid] = g_ab[C1 + tid];
    __syncthreads();

    float acc[4][4][4];
#pragma unroll
    for (int i = 0; i < 4; i++)
#pragma unroll
        for (int j = 0; j < 4; j++)
#pragma unroll
            for (int k = 0; k < 4; k++) acc[i][j][k] = 0.f;

    float2 ev[8];
#pragma unroll
    for (int l = 0; l < 8; l++) {
        int idx = l * 256 + tid;
        int r = idx >> 4, kp2 = idx & 15;
        ev[l] = *(const float2*)(g_Y1 + (m0 + r) * C1 + 2 * kp2);
    }
    {
        uint32_t (*pA)[128][20] = (uint32_t(*)[128][20])dyn;
#pragma unroll
        for (int l = 0; l < 8; l++) {
            int idx = l * 256 + tid;
            int r = idx >> 4, kp2 = idx & 15;
            int ch = 2 * kp2;
            float2 v = ev[l];
            v.x = lrelu(fmaf(sBNa[ch],     v.x, sBNc[ch]));
            v.y = lrelu(fmaf(sBNa[ch + 1], v.y, sBNc[ch + 1]));
            uint16_t h0, l0, h1, l1;
            bsplit(v.x, h0, l0); bsplit(v.y, h1, l1);
            pA[0][r][kp2] = pk(h0, h1);
            pA[1][r][kp2] = pk(l0, l1);
        }
    }
#pragma unroll
    for (int l = 0; l < 8; l++) {
        int idx = l * 256 + tid;
        int r = idx >> 4, kp2 = idx & 15;
        ev[l] = *(const float2*)(g_Y1 + (m0 + r) * C1 + 32 + 2 * kp2);
    }
#pragma unroll
    for (int l = 0; l < 4; l++) {
        int idx = l * 256 + tid;
        int pb = idx >> 9, rem = idx & 511, n = rem >> 2, c4 = (rem & 3) * 4;
        cpasync16(bBs + ((pb * 128 + n) * 20 + c4) * 4,
                  g_W2s + (size_t)pb * C2 * 128 + (size_t)n * 128 + c4);
    }
    CP_COMMIT();
    CP_WAIT0();
    __syncthreads();

    for (int it = 0; it < 8; it++) {
        const int cur = it & 1;
        const int nxt = cur ^ 1;
        if (it < 7) {
            const int kh = (it + 1) * 16;
#pragma unroll
            for (int l = 0; l < 4; l++) {
                int idx = l * 256 + tid;
                int pb = idx >> 9, rem = idx & 511, n = rem >> 2, c4 = (rem & 3) * 4;
                cpasync16(bBs + nxt * 2 * PLANE + ((pb * 128 + n) * 20 + c4) * 4,
                          g_W2s + (size_t)pb * C2 * 128 + (size_t)n * 128 + kh + c4);
            }
            CP_COMMIT();
        }
        compute_chunk(aA + cur * 2 * PLANE, bBs + cur * 2 * PLANE, acc, wr, wc, lane);
        if (it < 7) {
            uint32_t (*pA)[128][20] = ((uint32_t(*)[128][20])dyn) + nxt * 2;
            const int k0 = (it + 1) * 32;
#pragma unroll
            for (int l = 0; l < 8; l++) {
                int idx = l * 256 + tid;
                int r = idx >> 4, kp2 = idx & 15;
                int ch = k0 + 2 * kp2;
                float2 v = ev[l];
                v.x = lrelu(fmaf(sBNa[ch],     v.x, sBNc[ch]));
                v.y = lrelu(fmaf(sBNa[ch + 1], v.y, sBNc[ch + 1]));
                uint16_t h0, l0, h1, l1;
                bsplit(v.x, h0, l0); bsplit(v.y, h1, l1);
                pA[0][r][kp2] = pk(h0, h1);
                pA[1][r][kp2] = pk(l0, l1);
            }
        }
        if (it < 6) {
#pragma unroll
            for (int l = 0; l < 8; l++) {
                int idx = l * 256 + tid;
                int r = idx >> 4, kp2 = idx & 15;
                ev[l] = *(const float2*)(g_Y1 + (m0 + r) * C1 + (it + 2) * 32 + 2 * kp2);
            }
        }
        if (it < 7) { CP_WAIT0(); __syncthreads(); }
    }

#pragma unroll
    for (int mf = 0; mf < 4; mf++) {
        int rl = wr * 64 + mf * 16 + (lane >> 2);
#pragma unroll
        for (int nf = 0; nf < 4; nf++) {
            int col = wc * 32 + nf * 8 + (lane & 3) * 2;
            float* d0 = out + (m0 + rl) * C2 + col;
            float* d1 = out + (m0 + rl + 8) * C2 + col;
            *(float2*)d0 = { acc[mf][nf][0], acc[mf][nf][1] };
            *(float2*)d1 = { acc[mf][nf][2], acc[mf][nf][3] };
        }
    }
    __syncthreads();
    stats_epilogue(acc, wr, wc, lane, tid, sPS, sPQ, 0, blockIdx.x);
}

// ============================================================
// finalize: one block per channel, reduce 1024 float partials in fp64
// ============================================================
template <int C>
__global__ __launch_bounds__(256) void k_finalizeF(
    const float* __restrict__ g, const float* __restrict__ bb, int aoff)
{
    __shared__ double ss[256], sq[256];
    const int c   = blockIdx.x;
    const int tid = threadIdx.x;
    double s = 0.0, q = 0.0;
    for (int i = tid; i < 1024; i += 256) {
        s += (double)g_partS[(size_t)c * 1024 + i];
        q += (double)g_partQ[(size_t)c * 1024 + i];
    }
    ss[tid] = s; sq[tid] = q;
    __syncthreads();
    for (int off = 128; off > 0; off >>= 1) {
        if (tid < off) { ss[tid] += ss[tid + off]; sq[tid] += sq[tid + off]; }
        __syncthreads();
    }
    if (tid == 0) {
        const double invM = 1.0 / (double)MTOT;
        double mean = ss[0] * invM;
        double var  = sq[0] * invM - mean * mean;
        float a = (float)((double)g[c] / sqrt(var + 1e-5));
        g_ab[aoff + c]     = a;
        g_ab[aoff + C + c] = (float)((double)bb[c] - mean * (double)a);
    }
}

__global__ __launch_bounds__(256) void k_bn_act2(float* __restrict__ Y)
{
    size_t i4 = (size_t)blockIdx.x * blockDim.x + threadIdx.x;
    int c4 = (int)(i4 & (C2 / 4 - 1)) * 4;
    float4 v  = ((float4*)Y)[i4];
    float4 av = *(const float4*)&g_ab[2 * C1 + c4];
    float4 cv = *(const float4*)&g_ab[2 * C1 + C2 + c4];
    v.x = lrelu(fmaf(av.x, v.x, cv.x));
    v.y = lrelu(fmaf(av.y, v.y, cv.y));
    v.z = lrelu(fmaf(av.z, v.z, cv.z));
    v.w = lrelu(fmaf(av.w, v.w, cv.w));
    ((float4*)Y)[i4] = v;
}

// ============================================================
extern "C" void kernel_launch(void* const* d_in, const int* in_sizes, int n_in,
                              void* d_out, int out_size)
{
    (void)in_sizes; (void)n_in; (void)out_size;
    const float* E0 = (const float*)d_in[0];
    const float* E1 = (const float*)d_in[1];
    const float* P  = (const float*)d_in[2];
    const float* W1 = (const float*)d_in[3];
    const float* g1 = (const float*)d_in[4];
    const float* b1 = (const float*)d_in[5];
    const float* W2 = (const float*)d_in[6];
    const float* g2 = (const float*)d_in[7];
    const float* b2 = (const float*)d_in[8];
    float* out = (float*)d_out;

    cudaFuncSetAttribute(k1_mma,  cudaFuncAttributeMaxDynamicSharedMemorySize, 61440);
    cudaFuncSetAttribute(k_gemm1, cudaFuncAttributeMaxDynamicSharedMemorySize, 81920);
    cudaFuncSetAttribute(k_gemm2, cudaFuncAttributeMaxDynamicSharedMemorySize, 81920);

    // 0. one-time conversions
    kP_split<<<dim3(MB, 8), 256>>>(P);
    kW_split<1><<<(C1 * 128) / 256, 256>>>(W1);
    kW_split<2><<<(C2 * 128) / 256, 256>>>(W2);

    // 1. edge aggregation (R10 structure: 2 CTAs/SM) -> g_Xs
    k1_mma<<<dim3(4, MB, 2), 256, 61440>>>(E0, E1);

    // 2. GEMM1 + fused BN1 stats
    k_gemm1<<<dim3(MTOT / 128, 2), 256, 81920>>>();
    k_finalizeF<C1><<<C1, 256>>>(g1, b1, 0);

    // 3. GEMM2 (BN1+LReLU on load) + fused BN2 stats
    k_gemm2<<<dim3(MTOT / 128, 1), 256, 81920>>>(out);
    k_finalizeF<C2><<<C2, 256>>>(g2, b2, 2 * C1);

    // 4. in-place BN2 + LReLU
    k_bn_act2<<<16384, 256>>>(out);
}

// round 13
// speedup vs baseline: 4.0683x; 1.0111x over previous
#include <cuda_runtime.h>
#include <cuda_bf16.h>
#include <cstdint>

// Problem constants
#define MB   256
#define NN   512
#define DD   128
#define C1   256
#define C2   128
#define MTOT (MB * NN)

// ---------------- scratch ----------------
__device__ uint32_t g_Pt[(size_t)MB * 2 * DD * (NN / 2)];
__device__ uint32_t g_Xs[2 * (size_t)MTOT * (C1 / 2)];
__device__ float    g_Y1[(size_t)MTOT * C1];
__device__ uint32_t g_W1s[2 * C1 * (C1 / 2)];
__device__ uint32_t g_W2s[2 * C2 * (C1 / 2)];
__device__ float    g_partS[256 * 1024];
__device__ float    g_partQ[256 * 1024];
__device__ float    g_ab[2 * C1 + 2 * C2];

__device__ __forceinline__ float lrelu(float y) { return y >= 0.f ? y : 0.01f * y; }

// ---------------- helpers ----------------
__device__ __forceinline__ void bsplit(float x, uint16_t& h, uint16_t& l) {
    __nv_bfloat16 hb = __float2bfloat16(x);
    float r = x - __bfloat162float(hb);
    __nv_bfloat16 lb = __float2bfloat16(r);
    h = __bfloat16_as_ushort(hb);
    l = __bfloat16_as_ushort(lb);
}
__device__ __forceinline__ uint32_t pk(uint16_t a, uint16_t b) {
    return (uint32_t)a | ((uint32_t)b << 16);
}
__device__ __forceinline__ uint32_t smem_u32(const void* p) {
    uint32_t a;
    asm("{ .reg .u64 t; cvta.to.shared.u64 t, %1; cvt.u32.u64 %0, t; }" : "=r"(a) : "l"(p));
    return a;
}
__device__ __forceinline__ void cpasync16(uint32_t saddr, const void* g) {
    asm volatile("cp.async.cg.shared.global [%0], [%1], 16;" :: "r"(saddr), "l"(g));
}
#define CP_COMMIT() asm volatile("cp.async.commit_group;" ::: "memory")
#define CP_WAIT0()  asm volatile("cp.async.wait_group 0;" ::: "memory")
#define CP_WAIT1()  asm volatile("cp.async.wait_group 1;" ::: "memory")

__device__ __forceinline__ void mma16816(float* c, const uint32_t* a, const uint32_t* b) {
    asm volatile(
        "mma.sync.aligned.m16n8k16.row.col.f32.bf16.bf16.f32 "
        "{%0,%1,%2,%3}, {%4,%5,%6,%7}, {%8,%9}, {%0,%1,%2,%3};"
        : "+f"(c[0]), "+f"(c[1]), "+f"(c[2]), "+f"(c[3])
        : "r"(a[0]), "r"(a[1]), "r"(a[2]), "r"(a[3]), "r"(b[0]), "r"(b[1]));
}
__device__ __forceinline__ void ldsm4(uint32_t& r0, uint32_t& r1, uint32_t& r2,
                                      uint32_t& r3, uint32_t a) {
    asm volatile("ldmatrix.sync.aligned.m8n8.x4.shared.b16 {%0,%1,%2,%3}, [%4];"
        : "=r"(r0), "=r"(r1), "=r"(r2), "=r"(r3) : "r"(a));
}

// ---------------- warp-tile compute over one 32-k chunk (ldmatrix) ----------
#define PLANE 10240u            // bytes per [128][20] u32 plane
__device__ __forceinline__ void compute_chunk(
    uint32_t aB, uint32_t bB, float acc[4][4][4], int wr, int wc, int lane)
{
    const int l7  = lane & 7;
    const int tb0 = (lane >> 3) & 1;
    const int tb1 = (lane >> 4) & 1;
#pragma unroll
    for (int ks = 0; ks < 2; ks++) {
        uint32_t ah[4][4], al[4][4], bh[2][4], bl[2][4];
#pragma unroll
        for (int mf = 0; mf < 4; mf++) {
            uint32_t off = ((uint32_t)(wr * 64 + mf * 16 + tb0 * 8 + l7) * 20
                            + (uint32_t)(ks * 8 + tb1 * 4)) * 4;
            ldsm4(ah[mf][0], ah[mf][1], ah[mf][2], ah[mf][3], aB + off);
            ldsm4(al[mf][0], al[mf][1], al[mf][2], al[mf][3], aB + PLANE + off);
        }
#pragma unroll
        for (int np = 0; np < 2; np++) {
            uint32_t off = ((uint32_t)(wc * 32 + np * 16 + tb1 * 8 + l7) * 20
                            + (uint32_t)(ks * 8 + tb0 * 4)) * 4;
            ldsm4(bh[np][0], bh[np][1], bh[np][2], bh[np][3], bB + off);
            ldsm4(bl[np][0], bl[np][1], bl[np][2], bl[np][3], bB + PLANE + off);
        }
#pragma unroll
        for (int mf = 0; mf < 4; mf++)
#pragma unroll
            for (int nf = 0; nf < 4; nf++)
                mma16816(acc[mf][nf], ah[mf], &bh[nf >> 1][(nf & 1) * 2]);
#pragma unroll
        for (int mf = 0; mf < 4; mf++)
#pragma unroll
            for (int nf = 0; nf < 4; nf++)
                mma16816(acc[mf][nf], ah[mf], &bl[nf >> 1][(nf & 1) * 2]);
#pragma unroll
        for (int mf = 0; mf < 4; mf++)
#pragma unroll
            for (int nf = 0; nf < 4; nf++)
                mma16816(acc[mf][nf], al[mf], &bh[nf >> 1][(nf & 1) * 2]);
    }
}

// ---------------- fused per-CTA BN stats epilogue (deterministic) ----------
__device__ __forceinline__ void stats_epilogue(
    const float acc[4][4][4], int wr, int wc, int lane, int tid,
    float* sPS, float* sPQ, int chBase, int bx)
{
    const int ci = wr * 8 + (lane >> 2);
#pragma unroll
    for (int nf = 0; nf < 4; nf++)
#pragma unroll
        for (int c01 = 0; c01 < 2; c01++) {
            int col = wc * 32 + nf * 8 + (lane & 3) * 2 + c01;
            float s = 0.f, q = 0.f;
#pragma unroll
            for (int mf = 0; mf < 4; mf++) {
                float y0 = acc[mf][nf][c01];
                float y1 = acc[mf][nf][2 + c01];
                s += y0 + y1;
                q += y0 * y0 + y1 * y1;
            }
            sPS[col * 17 + ci] = s;
            sPQ[col * 17 + ci] = q;
        }
    __syncthreads();
    if (tid < 128) {
        float s = 0.f, q = 0.f;
#pragma unroll
        for (int i = 0; i < 16; i++) {
            s += sPS[tid * 17 + i];
            q += sPQ[tid * 17 + i];
        }
        g_partS[(size_t)(chBase + tid) * 1024 + bx] = s;
        g_partQ[(size_t)(chBase + tid) * 1024 + bx] = q;
    }
}

// ============================================================
// kP: P -> transposed split planes g_Pt[b][pa][d][kp]
// ============================================================
__global__ __launch_bounds__(256) void kP_split(const float* __restrict__ P)
{
    __shared__ uint16_t sH16[128][66];
    __shared__ uint16_t sL16[128][66];

    const int tid = threadIdx.x;
    const int b   = blockIdx.x;
    const int kt  = blockIdx.y;
    const float* __restrict__ Pb = P + ((size_t)b * NN + kt * 64) * DD;

#pragma unroll
    for (int l = 0; l < 16; l++) {
        int idx = l * 256 + tid;
        int k   = idx >> 6;
        int d2  = idx & 63;
        float2 v = *(const float2*)(Pb + (size_t)k * DD + 2 * d2);
        uint16_t h0, l0, h1, l1;
        bsplit(v.x, h0, l0); bsplit(v.y, h1, l1);
        sH16[2 * d2][k]     = h0; sL16[2 * d2][k]     = l0;
        sH16[2 * d2 + 1][k] = h1; sL16[2 * d2 + 1][k] = l1;
    }
    __syncthreads();
#pragma unroll
    for (int l = 0; l < 32; l++) {
        int idx = l * 256 + tid;
        int pa  = idx >> 12;
        int rem = idx & 4095;
        int d   = rem >> 5;
        int kp  = rem & 31;
        const uint16_t* s = pa ? &sL16[d][0] : &sH16[d][0];
        g_Pt[(((size_t)b * 2 + pa) * DD + d) * (NN / 2) + kt * 32 + kp] =
            pk(s[2 * kp], s[2 * kp + 1]);
    }
}

// ============================================================
// kW: weight split
// ============================================================
template <int WS>
__global__ __launch_bounds__(256) void kW_split(const float* __restrict__ W)
{
    uint32_t* dst = (WS == 1) ? g_W1s : g_W2s;
    const int OC  = (WS == 1) ? C1 : C2;
    int idx = blockIdx.x * 256 + threadIdx.x;
    int o   = idx >> 7;
    int kp  = idx & 127;
    if (o >= OC) return;
    float2 v = *(const float2*)(W + (size_t)o * C1 + 2 * kp);
    uint16_t h0, l0, h1, l1;
    bsplit(v.x, h0, l0); bsplit(v.y, h1, l1);
    dst[(size_t)o * 128 + kp]                    = pk(h0, h1);
    dst[(size_t)OC * 128 + (size_t)o * 128 + kp] = pk(l0, l1);
}

// ============================================================
// K1: single-buffered shA (E reg-prefetch conversion, STS.64 pairs),
//   3-stage cp.async ring for shB (wait_group 1), 2 barriers/iter,
//   81920B dyn smem, 128 regs -> 2 CTAs/SM.
// ============================================================
__global__ __launch_bounds__(256) void k1_mma(
    const float* __restrict__ E0, const float* __restrict__ E1)
{
    extern __shared__ uint32_t dyn[];
    __shared__ float sRow[128];
    __shared__ float sInv[128];

    const int tid  = threadIdx.x;
    const int lane = tid & 31;
    const int wid  = tid >> 5;
    const int wr   = wid & 1;
    const int wc   = wid >> 1;
    const int b    = blockIdx.y;
    const int ez   = blockIdx.z;
    const int row0 = blockIdx.x * 128;
    const float* __restrict__ E = (ez ? E1 : E0) + (size_t)b * NN * NN;
    const uint32_t* __restrict__ Pt = g_Pt + (size_t)b * 2 * DD * (NN / 2);
    const uint32_t aA = smem_u32(dyn);            // shA: 2 planes
    const uint32_t bB = aA + 2 * PLANE;           // shB: 3-stage ring x 2 planes

    float acc[4][4][4];
#pragma unroll
    for (int i = 0; i < 4; i++)
#pragma unroll
        for (int j = 0; j < 4; j++)
#pragma unroll
            for (int k = 0; k < 4; k++) acc[i][j][k] = 0.f;

    const int q4 = (tid & 7) * 4;
    int rl[4];
#pragma unroll
    for (int l = 0; l < 4; l++) rl[l] = l * 32 + (tid >> 3);
    float rs[4] = {0.f, 0.f, 0.f, 0.f};

    float4 ev[4];
#pragma unroll
    for (int l = 0; l < 4; l++)
        ev[l] = *(const float4*)(E + (size_t)(row0 + rl[l]) * NN + q4);
    // prologue: stage 0 (it0) and stage 1 (it1) cp.async groups
#pragma unroll
    for (int st = 0; st < 2; st++) {
#pragma unroll
        for (int l = 0; l < 4; l++) {
            int idx = l * 256 + tid;
            int pb = idx >> 9, rem = idx & 511, n = rem >> 2, c4 = (rem & 3) * 4;
            cpasync16(bB + st * 2 * PLANE + ((pb * 128 + n) * 20 + c4) * 4,
                      Pt + ((size_t)pb * DD + n) * (NN / 2) + st * 16 + c4);
        }
        CP_COMMIT();
    }

    for (int it = 0; it < 16; it++) {
        const int k0  = it * 32;
        const int cur = it % 3;
        CP_WAIT1();                           // stage cur ready
        __syncthreads();

        // convert E regs -> shA (STS.64 pairs); accumulate raw masked row-sum
#pragma unroll
        for (int l = 0; l < 4; l++) {
            int grow = row0 + rl[l];
            int gk   = k0 + q4;
            float4 v = ev[l];
            if (grow == gk)     v.x = 0.f;
            if (grow == gk + 1) v.y = 0.f;
            if (grow == gk + 2) v.z = 0.f;
            if (grow == gk + 3) v.w = 0.f;
            rs[l] += (v.x + v.y) + (v.z + v.w);
            uint16_t h0, l0, h1, l1, h2, l2, h3, l3;
            bsplit(v.x, h0, l0); bsplit(v.y, h1, l1);
            bsplit(v.z, h2, l2); bsplit(v.w, h3, l3);
            int kp = (tid & 7) * 2;
            uint2 hiw = { pk(h0, h1), pk(h2, h3) };
            uint2 low = { pk(l0, l1), pk(l2, l3) };
            *(uint2*)(dyn + (size_t)0 * 2560 + rl[l] * 20 + kp) = hiw;
            *(uint2*)(dyn + (size_t)1 * 2560 + rl[l] * 20 + kp) = low;
        }
        if (it < 15) {
#pragma unroll
            for (int l = 0; l < 4; l++)
                ev[l] = *(const float4*)(E + (size_t)(row0 + rl[l]) * NN + k0 + 32 + q4);
        }
        __syncthreads();

        if (it < 14) {
            const int st = (it + 2) % 3;
            const int kh = (it + 2) * 16;
#pragma unroll
            for (int l = 0; l < 4; l++) {
                int idx = l * 256 + tid;
                int pb = idx >> 9, rem = idx & 511, n = rem >> 2, c4 = (rem & 3) * 4;
                cpasync16(bB + st * 2 * PLANE + ((pb * 128 + n) * 20 + c4) * 4,
                          Pt + ((size_t)pb * DD + n) * (NN / 2) + kh + c4);
            }
            CP_COMMIT();
        } else {
            CP_COMMIT();                      // keep group count in lockstep
        }
        compute_chunk(aA, bB + cur * 2 * PLANE, acc, wr, wc, lane);
    }

#pragma unroll
    for (int l = 0; l < 4; l++) {
        float v = rs[l];
        v += __shfl_down_sync(0xffffffffu, v, 4);
        v += __shfl_down_sync(0xffffffffu, v, 2);
        v += __shfl_down_sync(0xffffffffu, v, 1);
        if ((tid & 7) == 0) sRow[rl[l]] = v;
    }
    __syncthreads();
    if (tid < 128) sInv[tid] = 1.0f / fmaxf(sRow[tid], 1e-12f);
    __syncthreads();

#pragma unroll
    for (int mf = 0; mf < 4; mf++) {
        int rll = wr * 64 + mf * 16 + (lane >> 2);
#pragma unroll
        for (int nf = 0; nf < 4; nf++) {
            int kpo = ez * 64 + wc * 16 + nf * 4 + (lane & 3);
            float i0 = sInv[rll], i1 = sInv[rll + 8];
            size_t m0r = (size_t)b * NN + row0 + rll;
            size_t m1r = m0r + 8;
            uint16_t h0, l0, h1, l1;
            bsplit(acc[mf][nf][0] * i0, h0, l0);
            bsplit(acc[mf][nf][1] * i0, h1, l1);
            g_Xs[m0r * 128 + kpo]                      = pk(h0, h1);
            g_Xs[(size_t)MTOT * 128 + m0r * 128 + kpo] = pk(l0, l1);
            bsplit(acc[mf][nf][2] * i1, h0, l0);
            bsplit(acc[mf][nf][3] * i1, h1, l1);
            g_Xs[m1r * 128 + kpo]                      = pk(h0, h1);
            g_Xs[(size_t)MTOT * 128 + m1r * 128 + kpo] = pk(l0, l1);
        }
    }
}

// ============================================================
// GEMM1: fully cp.async double-buffered + fused BN1 stats epilogue
// ============================================================
__global__ __launch_bounds__(256) void k_gemm1(void)
{
    extern __shared__ uint32_t dyn[];
    __shared__ float sPS[128 * 17], sPQ[128 * 17];

    const int tid  = threadIdx.x;
    const int lane = tid & 31;
    const int wid  = tid >> 5;
    const int wr   = wid & 1;
    const int wc   = wid >> 1;
    const size_t m0 = (size_t)blockIdx.x * 128;
    const int    o0 = blockIdx.y * 128;
    const uint32_t bA  = smem_u32(dyn);
    const uint32_t bBs = bA + 4 * PLANE;

    float acc[4][4][4];
#pragma unroll
    for (int i = 0; i < 4; i++)
#pragma unroll
        for (int j = 0; j < 4; j++)
#pragma unroll
            for (int k = 0; k < 4; k++) acc[i][j][k] = 0.f;

#pragma unroll
    for (int l = 0; l < 4; l++) {
        int idx = l * 256 + tid;
        int pa = idx >> 9, rem = idx & 511, r = rem >> 2, c4 = (rem & 3) * 4;
        cpasync16(bA + ((pa * 128 + r) * 20 + c4) * 4,
                  g_Xs + (size_t)pa * MTOT * 128 + (m0 + r) * 128 + c4);
        cpasync16(bBs + ((pa * 128 + r) * 20 + c4) * 4,
                  g_W1s + (size_t)pa * C1 * 128 + (size_t)(o0 + r) * 128 + c4);
    }
    CP_COMMIT();

    for (int it = 0; it < 8; it++) {
        const int cur = it & 1;
        CP_WAIT0();
        __syncthreads();
        if (it < 7) {
            const int kh = (it + 1) * 16;
#pragma unroll
            for (int l = 0; l < 4; l++) {
                int idx = l * 256 + tid;
                int pa = idx >> 9, rem = idx & 511, r = rem >> 2, c4 = (rem & 3) * 4;
                cpasync16(bA + (1 - cur) * 2 * PLANE + ((pa * 128 + r) * 20 + c4) * 4,
                          g_Xs + (size_t)pa * MTOT * 128 + (m0 + r) * 128 + kh + c4);
                cpasync16(bBs + (1 - cur) * 2 * PLANE + ((pa * 128 + r) * 20 + c4) * 4,
                          g_W1s + (size_t)pa * C1 * 128 + (size_t)(o0 + r) * 128 + kh + c4);
            }
            CP_COMMIT();
        }
        compute_chunk(bA + cur * 2 * PLANE, bBs + cur * 2 * PLANE, acc, wr, wc, lane);
    }

#pragma unroll
    for (int mf = 0; mf < 4; mf++) {
        int rl = wr * 64 + mf * 16 + (lane >> 2);
#pragma unroll
        for (int nf = 0; nf < 4; nf++) {
            int col = o0 + wc * 32 + nf * 8 + (lane & 3) * 2;
            float* d0 = g_Y1 + (m0 + rl) * C1 + col;
            float* d1 = g_Y1 + (m0 + rl + 8) * C1 + col;
            *(float2*)d0 = { acc[mf][nf][0], acc[mf][nf][1] };
            *(float2*)d1 = { acc[mf][nf][2], acc[mf][nf][3] };
        }
    }
    __syncthreads();
    stats_epilogue(acc, wr, wc, lane, tid, sPS, sPQ, o0, blockIdx.x);
}

// ============================================================
// GEMM2: A = bn1+lrelu(g_Y1), conversion pipelined into shA[nxt];
//   1 barrier/iter; fused BN2 stats epilogue
// ============================================================
__global__ __launch_bounds__(256) void k_gemm2(float* __restrict__ out)
{
    extern __shared__ uint32_t dyn[];
    __shared__ float sBNa[C1], sBNc[C1];
    __shared__ float sPS[128 * 17], sPQ[128 * 17];

    const int tid  = threadIdx.x;
    const int lane = tid & 31;
    const int wid  = tid >> 5;
    const int wr   = wid & 1;
    const int wc   = wid >> 1;
    const size_t m0 = (size_t)blockIdx.x * 128;
    const uint32_t aA  = smem_u32(dyn);           // shA: 2 bufs x 2 planes
    const uint32_t bBs = aA + 4 * PLANE;          // shB: 2 bufs x 2 planes

    sBNa[tid] = g_ab[tid];
    sBNc[tid] = g_ab[C1 + tid];
    __syncthreads();

    float acc[4][4][4];
#pragma unroll
    for (int i = 0; i < 4; i++)
#pragma unroll
        for (int j = 0; j < 4; j++)
#pragma unroll
            for (int k = 0; k < 4; k++) acc[i][j][k] = 0.f;

    float2 ev[8];
#pragma unroll
    for (int l = 0; l < 8; l++) {
        int idx = l * 256 + tid;
        int r = idx >> 4, kp2 = idx & 15;
        ev[l] = *(const float2*)(g_Y1 + (m0 + r) * C1 + 2 * kp2);
    }
    {
        uint32_t (*pA)[128][20] = (uint32_t(*)[128][20])dyn;
#pragma unroll
        for (int l = 0; l < 8; l++) {
            int idx = l * 256 + tid;
            int r = idx >> 4, kp2 = idx & 15;
            int ch = 2 * kp2;
            float2 v = ev[l];
            v.x = lrelu(fmaf(sBNa[ch],     v.x, sBNc[ch]));
            v.y = lrelu(fmaf(sBNa[ch + 1], v.y, sBNc[ch + 1]));
            uint16_t h0, l0, h1, l1;
            bsplit(v.x, h0, l0); bsplit(v.y, h1, l1);
            pA[0][r][kp2] = pk(h0, h1);
            pA[1][r][kp2] = pk(l0, l1);
        }
    }
#pragma unroll
    for (int l = 0; l < 8; l++) {
        int idx = l * 256 + tid;
        int r = idx >> 4, kp2 = idx & 15;
        ev[l] = *(const float2*)(g_Y1 + (m0 + r) * C1 + 32 + 2 * kp2);
    }
#pragma unroll
    for (int l = 0; l < 4; l++) {
        int idx = l * 256 + tid;
        int pb = idx >> 9, rem = idx & 511, n = rem >> 2, c4 = (rem & 3) * 4;
        cpasync16(bBs + ((pb * 128 + n) * 20 + c4) * 4,
                  g_W2s + (size_t)pb * C2 * 128 + (size_t)n * 128 + c4);
    }
    CP_COMMIT();
    CP_WAIT0();
    __syncthreads();

    for (int it = 0; it < 8; it++) {
        const int cur = it & 1;
        const int nxt = cur ^ 1;
        if (it < 7) {
            const int kh = (it + 1) * 16;
#pragma unroll
            for (int l = 0; l < 4; l++) {
                int idx = l * 256 + tid;
                int pb = idx >> 9, rem = idx & 511, n = rem >> 2, c4 = (rem & 3) * 4;
                cpasync16(bBs + nxt * 2 * PLANE + ((pb * 128 + n) * 20 + c4) * 4,
                          g_W2s + (size_t)pb * C2 * 128 + (size_t)n * 128 + kh + c4);
            }
            CP_COMMIT();
        }
        compute_chunk(aA + cur * 2 * PLANE, bBs + cur * 2 * PLANE, acc, wr, wc, lane);
        if (it < 7) {
            uint32_t (*pA)[128][20] = ((uint32_t(*)[128][20])dyn) + nxt * 2;
            const int k0 = (it + 1) * 32;
#pragma unroll
            for (int l = 0; l < 8; l++) {
                int idx = l * 256 + tid;
                int r = idx >> 4, kp2 = idx & 15;
                int ch = k0 + 2 * kp2;
                float2 v = ev[l];
                v.x = lrelu(fmaf(sBNa[ch],     v.x, sBNc[ch]));
                v.y = lrelu(fmaf(sBNa[ch + 1], v.y, sBNc[ch + 1]));
                uint16_t h0, l0, h1, l1;
                bsplit(v.x, h0, l0); bsplit(v.y, h1, l1);
                pA[0][r][kp2] = pk(h0, h1);
                pA[1][r][kp2] = pk(l0, l1);
            }
        }
        if (it < 6) {
#pragma unroll
            for (int l = 0; l < 8; l++) {
                int idx = l * 256 + tid;
                int r = idx >> 4, kp2 = idx & 15;
                ev[l] = *(const float2*)(g_Y1 + (m0 + r) * C1 + (it + 2) * 32 + 2 * kp2);
            }
        }
        if (it < 7) { CP_WAIT0(); __syncthreads(); }
    }

#pragma unroll
    for (int mf = 0; mf < 4; mf++) {
        int rl = wr * 64 + mf * 16 + (lane >> 2);
#pragma unroll
        for (int nf = 0; nf < 4; nf++) {
            int col = wc * 32 + nf * 8 + (lane & 3) * 2;
            float* d0 = out + (m0 + rl) * C2 + col;
            float* d1 = out + (m0 + rl + 8) * C2 + col;
            *(float2*)d0 = { acc[mf][nf][0], acc[mf][nf][1] };
            *(float2*)d1 = { acc[mf][nf][2], acc[mf][nf][3] };
        }
    }
    __syncthreads();
    stats_epilogue(acc, wr, wc, lane, tid, sPS, sPQ, 0, blockIdx.x);
}

// ============================================================
// finalize: one block per channel, reduce 1024 float partials in fp64
// ============================================================
template <int C>
__global__ __launch_bounds__(256) void k_finalizeF(
    const float* __restrict__ g, const float* __restrict__ bb, int aoff)
{
    __shared__ double ss[256], sq[256];
    const int c   = blockIdx.x;
    const int tid = threadIdx.x;
    double s = 0.0, q = 0.0;
    for (int i = tid; i < 1024; i += 256) {
        s += (double)g_partS[(size_t)c * 1024 + i];
        q += (double)g_partQ[(size_t)c * 1024 + i];
    }
    ss[tid] = s; sq[tid] = q;
    __syncthreads();
    for (int off = 128; off > 0; off >>= 1) {
        if (tid < off) { ss[tid] += ss[tid + off]; sq[tid] += sq[tid + off]; }
        __syncthreads();
    }
    if (tid == 0) {
        const double invM = 1.0 / (double)MTOT;
        double mean = ss[0] * invM;
        double var  = sq[0] * invM - mean * mean;
        float a = (float)((double)g[c] / sqrt(var + 1e-5));
        g_ab[aoff + c]     = a;
        g_ab[aoff + C + c] = (float)((double)bb[c] - mean * (double)a);
    }
}

__global__ __launch_bounds__(256) void k_bn_act2(float* __restrict__ Y)
{
    size_t i4 = (size_t)blockIdx.x * blockDim.x + threadIdx.x;
    int c4 = (int)(i4 & (C2 / 4 - 1)) * 4;
    float4 v  = ((float4*)Y)[i4];
    float4 av = *(const float4*)&g_ab[2 * C1 + c4];
    float4 cv = *(const float4*)&g_ab[2 * C1 + C2 + c4];
    v.x = lrelu(fmaf(av.x, v.x, cv.x));
    v.y = lrelu(fmaf(av.y, v.y, cv.y));
    v.z = lrelu(fmaf(av.z, v.z, cv.z));
    v.w = lrelu(fmaf(av.w, v.w, cv.w));
    ((float4*)Y)[i4] = v;
}

// ============================================================
extern "C" void kernel_launch(void* const* d_in, const int* in_sizes, int n_in,
                              void* d_out, int out_size)
{
    (void)in_sizes; (void)n_in; (void)out_size;
    const float* E0 = (const float*)d_in[0];
    const float* E1 = (const float*)d_in[1];
    const float* P  = (const float*)d_in[2];
    const float* W1 = (const float*)d_in[3];
    const float* g1 = (const float*)d_in[4];
    const float* b1 = (const float*)d_in[5];
    const float* W2 = (const float*)d_in[6];
    const float* g2 = (const float*)d_in[7];
    const float* b2 = (const float*)d_in[8];
    float* out = (float*)d_out;

    cudaFuncSetAttribute(k1_mma,  cudaFuncAttributeMaxDynamicSharedMemorySize, 81920);
    cudaFuncSetAttribute(k_gemm1, cudaFuncAttributeMaxDynamicSharedMemorySize, 81920);
    cudaFuncSetAttribute(k_gemm2, cudaFuncAttributeMaxDynamicSharedMemorySize, 81920);

    // 0. one-time conversions
    kP_split<<<dim3(MB, 8), 256>>>(P);
    kW_split<1><<<(C1 * 128) / 256, 256>>>(W1);
    kW_split<2><<<(C2 * 128) / 256, 256>>>(W2);

    // 1. edge aggregation (3-stage B ring, 2 CTAs/SM) -> g_Xs
    k1_mma<<<dim3(4, MB, 2), 256, 81920>>>(E0, E1);

    // 2. GEMM1 + fused BN1 stats
    k_gemm1<<<dim3(MTOT / 128, 2), 256, 81920>>>();
    k_finalizeF<C1><<<C1, 256>>>(g1, b1, 0);

    // 3. GEMM2 (BN1+LReLU on load) + fused BN2 stats
    k_gemm2<<<dim3(MTOT / 128, 1), 256, 81920>>>(out);
    k_finalizeF<C2><<<C2, 256>>>(g2, b2, 2 * C1);

    // 4. in-place BN2 + LReLU
    k_bn_act2<<<16384, 256>>>(out);
}